// round 14
// baseline (speedup 1.0000x reference)
#include <cuda_runtime.h>
#include <stdint.h>

// ---------------- problem constants ----------------
constexpr int BATCH = 4, SEQ = 1024, CH = 768, HEADS = 12, HDIM = 64;
constexpr int ROWS = BATCH * SEQ;   // 4096
constexpr int C3v  = 3 * CH;        // 2304
constexpr int NBH  = BATCH * HEADS; // 48

// ---------------- scratch ----------------
__device__ __align__(256) int8_t g_x0q [ROWS * CH];
__device__ __align__(256) int8_t g_wqkv[C3v * CH];
__device__            int    g_biasi[C3v];
__device__ __align__(256) int8_t g_wproj[CH * CH];
__device__ __align__(256) float  g_rw  [C3v + CH];
__device__ __align__(256) int8_t g_q2  [NBH * SEQ * HDIM];
__device__ __align__(256) int8_t g_k2  [NBH * SEQ * HDIM];
__device__ __align__(256) int8_t g_v2t [NBH * HDIM * SEQ];
__device__ __align__(256) int8_t g_x1q [ROWS * CH];
// 0:a_in 1:aq 2:ak 3:av 4:am 5:ap 6:LOG2E*hs*aq*ak 7:am*av 8:1/a_in 9:(am*av)/ap
__device__            float  g_sc[12];

__device__ __forceinline__ float clip8(float x) { return fminf(fmaxf(x, -8.f), 7.f); }
__device__ __forceinline__ int8_t q8(float x) { return (int8_t)__float2int_rn(clip8(x)); }
__device__ __forceinline__ int8_t q8p(float x) { return (int8_t)__float2int_rn(fminf(x, 7.f)); }

__device__ __forceinline__ float pexp2i(int acc, float s6p) {
    return __int_as_float(__float2int_rn(fmaf((float)acc, s6p, 1065353216.0f)));
}

__device__ __forceinline__ void cp16(void* dst, const void* src) {
    uint32_t d = (uint32_t)__cvta_generic_to_shared(dst);
    asm volatile("cp.async.cg.shared.global [%0], [%1], 16;" :: "r"(d), "l"(src));
}
#define CP_COMMIT() asm volatile("cp.async.commit_group;")
#define CP_WAIT1()  asm volatile("cp.async.wait_group 1;")
#define CP_WAIT0()  asm volatile("cp.async.wait_group 0;")

__device__ __forceinline__ uint32_t smem_u32(const void* p) {
    return (uint32_t)__cvta_generic_to_shared(p);
}
__device__ __forceinline__ void ldsm4(uint32_t addr, uint32_t& r0, uint32_t& r1,
                                      uint32_t& r2, uint32_t& r3) {
    asm volatile("ldmatrix.sync.aligned.m8n8.x4.shared.b16 {%0,%1,%2,%3}, [%4];"
                 : "=r"(r0), "=r"(r1), "=r"(r2), "=r"(r3) : "r"(addr));
}
#define MMA_S8(acc, a0, a1, a2, a3, b0, b1) \
    asm volatile("mma.sync.aligned.m16n8k32.row.col.s32.s8.s8.s32 " \
                 "{%0,%1,%2,%3},{%4,%5,%6,%7},{%8,%9},{%0,%1,%2,%3};" \
                 : "+r"((acc)[0]), "+r"((acc)[1]), "+r"((acc)[2]), "+r"((acc)[3]) \
                 : "r"(a0), "r"(a1), "r"(a2), "r"(a3), "r"(b0), "r"(b1))

// ---------------- pre ----------------
__global__ void k_pre(const float* __restrict__ qkv_act_alpha,
                      const float* __restrict__ proj_act_alpha,
                      const float* __restrict__ q_alpha,
                      const float* __restrict__ k_alpha,
                      const float* __restrict__ v_alpha,
                      const float* __restrict__ attn_alpha,
                      const float* __restrict__ qkv_alpha,
                      const float* __restrict__ proj_alpha,
                      const float* __restrict__ qkv_b) {
    __shared__ float sh[256];
    int t = threadIdx.x;
    for (int i = t; i < C3v + CH; i += 256)
        g_rw[i] = 1.0f / (i < C3v ? qkv_alpha[i] : proj_alpha[i - C3v]);
    float s = 0.f;
    for (int i = t; i < CH; i += 256) s += qkv_act_alpha[i];
    sh[t] = s; __syncthreads();
    for (int o = 128; o > 0; o >>= 1) { if (t < o) sh[t] += sh[t + o]; __syncthreads(); }
    float a_in = sh[0] / (float)CH;
    __syncthreads();
    for (int o = t; o < C3v; o += 256)
        g_biasi[o] = (int)truncf(qkv_b[o] / a_in / qkv_alpha[o]);
    s = 0.f;
    for (int i = t; i < CH; i += 256) s += proj_act_alpha[i];
    sh[t] = s; __syncthreads();
    for (int o = 128; o > 0; o >>= 1) { if (t < o) sh[t] += sh[t + o]; __syncthreads(); }
    float ap = sh[0] / (float)CH;
    if (t == 0) {
        float aq = 0.f, ak = 0.f, av = 0.f, am = 0.f;
        for (int i = 0; i < HEADS; i++) { aq += q_alpha[i]; ak += k_alpha[i]; av += v_alpha[i]; am += attn_alpha[i]; }
        aq /= HEADS; ak /= HEADS; av /= HEADS; am /= HEADS;
        g_sc[0] = a_in; g_sc[1] = aq; g_sc[2] = ak; g_sc[3] = av; g_sc[4] = am; g_sc[5] = ap;
        g_sc[6] = 1.4426950408889634f * ((0.125f * aq) * ak);
        g_sc[7] = am * av;
        g_sc[8] = 1.0f / a_in;
        g_sc[9] = (am * av) / ap;
    }
}

// ---------------- fused quantizer: 16 outputs per thread ----------------
constexpr int NG_X0 = ROWS * CH / 16;   // 196608 groups of 16
constexpr int NG_WQ = C3v * CH / 16;    // 110592
constexpr int NG_WP = CH * CH / 16;     // 36864
constexpr int NG_ALL = NG_X0 + NG_WQ + NG_WP;

__device__ __forceinline__ uint32_t pack4(float a, float b, float c, float d) {
    return (uint32_t)(uint8_t)q8(a) | ((uint32_t)(uint8_t)q8(b) << 8) |
           ((uint32_t)(uint8_t)q8(c) << 16) | ((uint32_t)(uint8_t)q8(d) << 24);
}

__global__ void k_quant_all(const float* __restrict__ x0,
                            const float* __restrict__ qkv_w,
                            const float* __restrict__ proj_w) {
    int i = blockIdx.x * blockDim.x + threadIdx.x;
    if (i >= NG_ALL) return;
    const float4* src;
    uint4* dst;
    float r;
    if (i < NG_X0) {
        src = (const float4*)x0 + i * 4;
        dst = (uint4*)g_x0q + i;
        r = g_sc[8];
    } else if (i < NG_X0 + NG_WQ) {
        int k = i - NG_X0;
        src = (const float4*)qkv_w + k * 4;
        dst = (uint4*)g_wqkv + k;
        r = g_rw[k / (CH / 16)];
    } else {
        int k = i - NG_X0 - NG_WQ;
        src = (const float4*)proj_w + k * 4;
        dst = (uint4*)g_wproj + k;
        r = g_rw[C3v + k / (CH / 16)];
    }
    float4 v0 = src[0], v1 = src[1], v2 = src[2], v3 = src[3];
    uint4 o;
    o.x = pack4(v0.x * r, v0.y * r, v0.z * r, v0.w * r);
    o.y = pack4(v1.x * r, v1.y * r, v1.z * r, v1.w * r);
    o.z = pack4(v2.x * r, v2.y * r, v2.z * r, v2.w * r);
    o.w = pack4(v3.x * r, v3.y * r, v3.z * r, v3.w * r);
    *dst = o;
}

// ---------------- int8 MMA GEMM, 3-stage cp.async ----------------
constexpr int GSM0 = 128 * 130 * 4;
constexpr int GSM1 = 3 * (128 + 64) * 80;
template <int MODE>
__global__ void __launch_bounds__(256, 2) gemm_s8(float* __restrict__ outf,
        const float* __restrict__ qkv_alpha,
        const float* __restrict__ nqw, const float* __restrict__ nqb,
        const float* __restrict__ nkw, const float* __restrict__ nkb,
        const float* __restrict__ e1, const float* __restrict__ e2) {
    constexpr int K  = 768;
    constexpr int BM = 128;
    constexpr int BN = (MODE == 0) ? 128 : 64;
    constexpr int BK = 64;
    constexpr int NTHR = 256;
    constexpr int WM = 64, WN = BN / 4;
    constexpr int MI = 4, NI = WN / 8;
    constexpr int SAS = BK + 16;
    constexpr int NK = K / BK;

    extern __shared__ __align__(16) int8_t dsm[];
    int8_t* As = dsm;
    int8_t* Bs = dsm + 3 * BM * SAS;

    // epilogue params staged in smem BEFORE the mainloop (latency overlapped)
    __shared__ float sA[130], sP1[130], sP2[130];
    __shared__ int   sBi[130], coef[64];

    const int8_t* A  = (MODE == 0) ? g_x0q  : g_x1q;
    const int8_t* Bw = (MODE == 0) ? g_wqkv : g_wproj;

    int tid = threadIdx.x;
    int warp = tid >> 5, lane = tid & 31;
    int wr = warp / 4, wc = warp % 4;
    int g = lane >> 2, q4 = lane & 3;
    int rowBase = blockIdx.y * BM;
    int colBase = blockIdx.x * BN;

    if constexpr (MODE == 0) {
        if (tid < 128) {
            int col = colBase + tid;
            int d = tid & 63, hs = tid >> 6;
            int idx = d * 2 + hs;
            int branch = col / CH;
            sBi[idx] = g_biasi[col];
            if (branch == 0) {
                float w = nqw[d];
                sA[idx]  = qkv_alpha[col];
                sP1[idx] = nqb[d] / w;
                sP2[idx] = w / g_sc[1];
            } else if (branch == 1) {
                float w = nkw[d];
                sA[idx]  = qkv_alpha[col];
                sP1[idx] = nkb[d] / w;
                sP2[idx] = w / g_sc[2];
            } else {
                sA[idx]  = (g_sc[0] * qkv_alpha[col]) / g_sc[3];
                sP1[idx] = 0.f; sP2[idx] = 0.f;
            }
        }
        if (tid < 64) coef[tid] = 1024 / (tid + 1);
    } else {
        // stage proj scale/bias for BN=64 columns
        if (tid < BN) {
            int cc = colBase + tid;
            sA[tid]  = e1[cc] * g_sc[5];
            sP1[tid] = e2[cc];
        }
    }

    uint32_t As_base = smem_u32(As);
    uint32_t Bs_base = smem_u32(Bs);
    uint32_t aoff = (uint32_t)(wr * WM + (lane & 15)) * SAS + ((lane >> 4) << 4);
    uint32_t boff = (uint32_t)(wc * WN + (lane & 7) + ((lane >> 4) << 3)) * SAS
                    + (((lane >> 3) & 1) << 4);

    auto load_stage = [&](int st, int k0) {
        #pragma unroll
        for (int idx = tid; idx < BM * BK / 16; idx += NTHR) {
            int r = idx / (BK / 16), seg = idx % (BK / 16);
            cp16(&As[st * BM * SAS + r * SAS + seg * 16],
                 &A[(long)(rowBase + r) * K + k0 + seg * 16]);
        }
        #pragma unroll
        for (int idx = tid; idx < BN * BK / 16; idx += NTHR) {
            int r = idx / (BK / 16), seg = idx % (BK / 16);
            cp16(&Bs[st * BN * SAS + r * SAS + seg * 16],
                 &Bw[(long)(colBase + r) * K + k0 + seg * 16]);
        }
    };

    int acc[MI][NI][4];
    #pragma unroll
    for (int i = 0; i < MI; i++)
        #pragma unroll
        for (int j = 0; j < NI; j++)
            #pragma unroll
            for (int v = 0; v < 4; v++) acc[i][j][v] = 0;

    load_stage(0, 0); CP_COMMIT();
    load_stage(1, BK); CP_COMMIT();

    for (int it = 0; it < NK; it++) {
        if (it < NK - 1) { CP_WAIT1(); } else { CP_WAIT0(); }
        __syncthreads();
        if (it + 2 < NK) { load_stage((it + 2) % 3, (it + 2) * BK); CP_COMMIT(); }

        int slot = it % 3;
        uint32_t Abase = As_base + (uint32_t)slot * (BM * SAS) + aoff;
        uint32_t Bbase = Bs_base + (uint32_t)slot * (BN * SAS) + boff;

        #pragma unroll
        for (int ks = 0; ks < BK; ks += 32) {
            uint32_t bfr[(NI + 1) / 2][4];
            #pragma unroll
            for (int jj = 0; jj < (NI + 1) / 2; jj++)
                ldsm4(Bbase + jj * (16 * SAS) + ks,
                      bfr[jj][0], bfr[jj][1], bfr[jj][2], bfr[jj][3]);
            #pragma unroll
            for (int i = 0; i < MI; i++) {
                uint32_t a0, a1, a2, a3;
                ldsm4(Abase + i * (16 * SAS) + ks, a0, a1, a2, a3);
                #pragma unroll
                for (int j = 0; j < NI; j++)
                    MMA_S8(acc[i][j], a0, a1, a2, a3,
                           bfr[j >> 1][(j & 1) * 2], bfr[j >> 1][(j & 1) * 2 + 1]);
            }
        }
    }
    __syncthreads();

    if constexpr (MODE == 1) {
        int rb = rowBase + wr * WM;
        int cb = wc * WN;
        #pragma unroll
        for (int i = 0; i < MI; i++)
            #pragma unroll
            for (int j = 0; j < NI; j++)
                #pragma unroll
                for (int v = 0; v < 4; v++) {
                    int rr = rb + i * 16 + g + (v >> 1) * 8;
                    int ccl = cb + j * 8 + q4 * 2 + (v & 1);
                    outf[(long)rr * CH + colBase + ccl] =
                        (float)acc[i][j][v] * sA[ccl] + sP1[ccl];
                }
    } else {
        int* sm32 = (int*)dsm;
        int rbL = wr * WM, cbL = wc * WN;
        #pragma unroll
        for (int i = 0; i < MI; i++)
            #pragma unroll
            for (int j = 0; j < NI; j++)
                #pragma unroll
                for (int v = 0; v < 4; v++) {
                    int rr = rbL + i * 16 + g + (v >> 1) * 8;
                    int cc = cbL + j * 8 + q4 * 2 + (v & 1);
                    sm32[rr * 130 + cc + (cc >> 6)] = acc[i][j][v];
                }
        __syncthreads();

        int r = tid >> 1, hs = tid & 1;
        int slice = (colBase >> 6) + hs;
        int branch = slice / HEADS;
        int hh = slice % HEADS;
        int rrG = rowBase + r;
        int bb = rrG >> 10, nn = rrG & 1023;
        int bhh = bb * HEADS + hh;
        const int base = r * 130 + hs * 65;

        if (branch < 2) {
            int m = 0, vv = 0;
            #pragma unroll 8
            for (int d = 0; d < HDIM; d++) {
                int ival = sm32[base + d] + sBi[d * 2 + hs];
                float xf = (float)ival * sA[d * 2 + hs];
                int xi = (int)xf;
                int dd = xi - m;
                m += (dd * coef[d]) >> 10;
                vv += dd * (xi - m);
            }
            float mu = (float)m;
            float invden = 1.0f / (sqrtf((float)vv * 0.015625f) + 1e-5f);
            uint32_t* outp = (uint32_t*)((branch == 0 ? g_q2 : g_k2)
                              + ((long)bhh * SEQ + nn) * HDIM);
            #pragma unroll 4
            for (int dw = 0; dw < 16; dw++) {
                uint32_t pk = 0;
                #pragma unroll
                for (int kk = 0; kk < 4; kk++) {
                    int d = dw * 4 + kk;
                    int ival = sm32[base + d] + sBi[d * 2 + hs];
                    float xf = (float)ival * sA[d * 2 + hs];
                    float q1 = (xf - mu) * invden;
                    pk |= ((uint32_t)(uint8_t)q8((q1 + sP1[d * 2 + hs]) * sP2[d * 2 + hs]))
                          << (kk * 8);
                }
                outp[dw] = pk;
            }
        } else {
            int8_t* outv = g_v2t + (long)bhh * HDIM * SEQ + nn;
            #pragma unroll 8
            for (int d = 0; d < HDIM; d++) {
                int ival = sm32[base + d] + sBi[d * 2 + hs];
                outv[d * SEQ] = q8((float)ival * sA[d * 2 + hs]);
            }
        }
    }
}

// ---------------- fused flash attention: quarter-streamed K/V, 3 CTAs/SM ----------------
constexpr int ATT_B0 = 0;
constexpr int ATT_B1 = 20480;
constexpr int ATT_A  = 40960;
constexpr int ATT_Q  = 57600;
constexpr int ATT_S  = 58880;
constexpr int SMEM_ATT = 58944;

__global__ void __launch_bounds__(256, 3) k_attn_fused() {
    extern __shared__ __align__(16) int8_t sh[];
    int8_t* B0  = sh + ATT_B0;
    int8_t* B1  = sh + ATT_B1;
    int8_t* Asm = sh + ATT_A;
    int8_t* Qsm = sh + ATT_Q;
    float*  rs  = (float*)(sh + ATT_S);

    int bh = blockIdx.y;
    int h = bh % HEADS, b = bh / HEADS;
    int qBase = blockIdx.x * 16;
    int tid = threadIdx.x, w = tid >> 5, lane = tid & 31;
    int g = lane >> 2, q4 = lane & 3;

    const int8_t* Qg = g_q2 + ((long)bh * SEQ + qBase) * HDIM;
    const int8_t* Kg = g_k2 + (long)bh * SEQ * HDIM;
    const int8_t* Vg = g_v2t + (long)bh * HDIM * SEQ;

    if (tid < 64) {
        int r = tid >> 2, s = tid & 3;
        cp16(&Qsm[r * 80 + s * 16], &Qg[r * 64 + s * 16]);
    }
    #pragma unroll
    for (int t2 = 0; t2 < 4; t2++) {
        int idx = tid + t2 * 256;
        int r = idx >> 2, s = idx & 3;
        cp16(&B0[r * 80 + s * 16], &Kg[r * 64 + s * 16]);
    }
    CP_COMMIT();
    #pragma unroll
    for (int t2 = 0; t2 < 4; t2++) {
        int idx = tid + t2 * 256;
        int r = idx >> 2, s = idx & 3;
        cp16(&B1[r * 80 + s * 16], &Kg[(256 + r) * 64 + s * 16]);
    }
    CP_COMMIT();
    if (tid < 16) rs[tid] = 0.f;
    CP_WAIT1();
    __syncthreads();

    uint32_t B0u = smem_u32(B0), B1u = smem_u32(B1);
    uint32_t Qu  = smem_u32(Qsm);
    uint32_t aoffQ = (uint32_t)(lane & 15) * 80 + ((lane >> 4) << 4);
    uint32_t kfoff = (uint32_t)(w * 32 + (lane & 7) + ((lane >> 4) << 3)) * 80
                     + (((lane >> 3) & 1) << 4);

    int acc[16][4];
    #pragma unroll
    for (int j = 0; j < 16; j++)
        #pragma unroll
        for (int v = 0; v < 4; v++) acc[j][v] = 0;

    #pragma unroll
    for (int qi = 0; qi < 4; qi++) {
        uint32_t bufU = (qi & 1) ? B1u : B0u;
        int8_t*  buf  = (qi & 1) ? B1 : B0;
        #pragma unroll
        for (int ks2 = 0; ks2 < 2; ks2++) {
            uint32_t a0, a1, a2, a3;
            ldsm4(Qu + aoffQ + ks2 * 32, a0, a1, a2, a3);
            #pragma unroll
            for (int p = 0; p < 2; p++) {
                uint32_t b0, b1, b2, b3;
                ldsm4(bufU + kfoff + (uint32_t)p * (16 * 80) + ks2 * 32, b0, b1, b2, b3);
                MMA_S8(acc[qi * 4 + 2 * p],     a0, a1, a2, a3, b0, b1);
                MMA_S8(acc[qi * 4 + 2 * p + 1], a0, a1, a2, a3, b2, b3);
            }
        }
        __syncthreads();
        if (qi < 2) {
            #pragma unroll
            for (int t2 = 0; t2 < 4; t2++) {
                int idx = tid + t2 * 256;
                int r = idx >> 2, s = idx & 3;
                cp16(&buf[r * 80 + s * 16], &Kg[((qi + 2) * 256 + r) * 64 + s * 16]);
            }
            CP_COMMIT();
            CP_WAIT1();
            __syncthreads();
        } else if (qi == 2) {
            #pragma unroll
            for (int t2 = 0; t2 < 4; t2++) {
                int idx = tid + t2 * 256;
                int d = idx >> 4, s = idx & 15;
                cp16(&buf[d * 272 + s * 16], &Vg[d * 1024 + s * 16]);
            }
            CP_COMMIT();
            CP_WAIT1();
            __syncthreads();
        } else {
            #pragma unroll
            for (int t2 = 0; t2 < 4; t2++) {
                int idx = tid + t2 * 256;
                int d = idx >> 4, s = idx & 15;
                cp16(&buf[d * 272 + s * 16], &Vg[d * 1024 + 256 + s * 16]);
            }
            CP_COMMIT();
        }
    }

    float s6p = g_sc[6] * 8388608.0f;
    float sum0 = 0.f, sum1 = 0.f;
    #pragma unroll
    for (int j = 0; j < 16; j++) {
        float p0 = pexp2i(acc[j][0], s6p);
        float p1 = pexp2i(acc[j][1], s6p);
        float p2 = pexp2i(acc[j][2], s6p);
        float p3 = pexp2i(acc[j][3], s6p);
        acc[j][0] = __float_as_int(p0); acc[j][1] = __float_as_int(p1);
        acc[j][2] = __float_as_int(p2); acc[j][3] = __float_as_int(p3);
        sum0 += p0 + p1;
        sum1 += p2 + p3;
    }
    sum0 += __shfl_xor_sync(0xffffffffu, sum0, 1);
    sum0 += __shfl_xor_sync(0xffffffffu, sum0, 2);
    sum1 += __shfl_xor_sync(0xffffffffu, sum1, 1);
    sum1 += __shfl_xor_sync(0xffffffffu, sum1, 2);
    if (q4 == 0) {
        atomicAdd(&rs[g], sum0);
        atomicAdd(&rs[g + 8], sum1);
    }
    __syncthreads();
    if (tid < 16) rs[tid] = 1.0f / (rs[tid] * g_sc[4]);
    __syncthreads();

    float iv0 = rs[g], iv1 = rs[g + 8];
    #pragma unroll
    for (int j = 0; j < 16; j++) {
        int col = (j >> 2) * 256 + w * 32 + (j & 3) * 8 + q4 * 2;
        uint8_t v0 = (uint8_t)q8p(__int_as_float(acc[j][0]) * iv0);
        uint8_t v1 = (uint8_t)q8p(__int_as_float(acc[j][1]) * iv0);
        *(uint16_t*)&Asm[g * 1040 + col] = (uint16_t)v0 | ((uint16_t)v1 << 8);
        uint8_t v2 = (uint8_t)q8p(__int_as_float(acc[j][2]) * iv1);
        uint8_t v3 = (uint8_t)q8p(__int_as_float(acc[j][3]) * iv1);
        *(uint16_t*)&Asm[(g + 8) * 1040 + col] = (uint16_t)v2 | ((uint16_t)v3 << 8);
    }
    CP_WAIT1();
    __syncthreads();

    uint32_t Aoff  = smem_u32(Asm) + (uint32_t)(lane & 15) * 1040 + ((lane >> 4) << 4);
    uint32_t Vfoff = (uint32_t)(w * 8 + (lane & 7)) * 272 + ((lane >> 3) << 4);

    int pv[4] = {0, 0, 0, 0};
    #pragma unroll
    for (int qv = 0; qv < 4; qv++) {
        uint32_t bufU = (qv & 1) ? B1u : B0u;
        int8_t*  buf  = (qv & 1) ? B1 : B0;
        uint32_t Abase = Aoff + (uint32_t)qv * 256;
        #pragma unroll
        for (int ksl = 0; ksl < 256; ksl += 64) {
            uint32_t va, vb, vc, vd;
            ldsm4(bufU + Vfoff + ksl, va, vb, vc, vd);
            uint32_t a0, a1, a2, a3;
            ldsm4(Abase + ksl, a0, a1, a2, a3);
            MMA_S8(pv, a0, a1, a2, a3, va, vb);
            ldsm4(Abase + ksl + 32, a0, a1, a2, a3);
            MMA_S8(pv, a0, a1, a2, a3, vc, vd);
        }
        if (qv < 2) {
            __syncthreads();
            #pragma unroll
            for (int t2 = 0; t2 < 4; t2++) {
                int idx = tid + t2 * 256;
                int d = idx >> 4, s = idx & 15;
                cp16(&buf[d * 272 + s * 16], &Vg[d * 1024 + (qv + 2) * 256 + s * 16]);
            }
            CP_COMMIT();
            CP_WAIT1();
            __syncthreads();
        } else if (qv == 2) {
            CP_WAIT0();
            __syncthreads();
        }
    }

    float r9 = g_sc[9];
    long base0 = ((long)(b * SEQ + qBase + g)) * CH + h * HDIM + w * 8 + q4 * 2;
    uint16_t pA = (uint16_t)(uint8_t)q8((float)pv[0] * r9)
                | ((uint16_t)(uint8_t)q8((float)pv[1] * r9) << 8);
    *(uint16_t*)&g_x1q[base0] = pA;
    uint16_t pB = (uint16_t)(uint8_t)q8((float)pv[2] * r9)
                | ((uint16_t)(uint8_t)q8((float)pv[3] * r9) << 8);
    *(uint16_t*)&g_x1q[base0 + 8L * CH] = pB;
}

// ---------------- launcher (serial, monolithic) ----------------
extern "C" void kernel_launch(void* const* d_in, const int* in_sizes, int n_in,
                              void* d_out, int out_size) {
    const float* x0             = (const float*)d_in[0];
    const float* qkv_w          = (const float*)d_in[1];
    const float* qkv_b          = (const float*)d_in[2];
    const float* qkv_alpha      = (const float*)d_in[3];
    const float* qkv_act_alpha  = (const float*)d_in[4];
    const float* proj_w         = (const float*)d_in[5];
    const float* proj_b         = (const float*)d_in[6];
    const float* proj_alpha     = (const float*)d_in[7];
    const float* proj_act_alpha = (const float*)d_in[8];
    const float* norm_q_w       = (const float*)d_in[9];
    const float* norm_q_b       = (const float*)d_in[10];
    const float* norm_k_w       = (const float*)d_in[11];
    const float* norm_k_b       = (const float*)d_in[12];
    const float* q_alpha        = (const float*)d_in[13];
    const float* k_alpha        = (const float*)d_in[14];
    const float* v_alpha        = (const float*)d_in[15];
    const float* attn_alpha     = (const float*)d_in[16];
    float* out = (float*)d_out;

    cudaFuncSetAttribute(k_attn_fused, cudaFuncAttributeMaxDynamicSharedMemorySize, SMEM_ATT);
    cudaFuncSetAttribute(gemm_s8<0>, cudaFuncAttributeMaxDynamicSharedMemorySize, GSM0);
    cudaFuncSetAttribute(gemm_s8<1>, cudaFuncAttributeMaxDynamicSharedMemorySize, GSM1);

    // 1
    k_pre<<<1, 256>>>(qkv_act_alpha, proj_act_alpha, q_alpha, k_alpha, v_alpha,
                      attn_alpha, qkv_alpha, proj_alpha, qkv_b);
    // 2: fused quantizer, 16B/thread
    k_quant_all<<<(NG_ALL + 255) / 256, 256>>>(x0, qkv_w, proj_w);
    // 3: QKV GEMM + fused norm
    gemm_s8<0><<<dim3(C3v / 128, ROWS / 128, 1), 256, GSM0>>>(
        nullptr, qkv_alpha, norm_q_w, norm_q_b, norm_k_w, norm_k_b, nullptr, nullptr);
    // 4: fused attention
    k_attn_fused<<<dim3(SEQ / 16, NBH), 256, SMEM_ATT>>>();
    // 5: projection GEMM (scale/bias staged in smem)
    gemm_s8<1><<<dim3(CH / 64, ROWS / 128, 1), 256, GSM1>>>(
        out, qkv_alpha, norm_q_w, norm_q_b, norm_k_w, norm_k_b, proj_alpha, proj_b);
}

// round 15
// speedup vs baseline: 1.0001x; 1.0001x over previous
#include <cuda_runtime.h>
#include <stdint.h>

// ---------------- problem constants ----------------
constexpr int BATCH = 4, SEQ = 1024, CH = 768, HEADS = 12, HDIM = 64;
constexpr int ROWS = BATCH * SEQ;   // 4096
constexpr int C3v  = 3 * CH;        // 2304
constexpr int NBH  = BATCH * HEADS; // 48

// ---------------- scratch ----------------
__device__ __align__(256) int8_t g_x0q [ROWS * CH];
__device__ __align__(256) int8_t g_wqkv[C3v * CH];
__device__            int    g_biasi[C3v];
__device__ __align__(256) int8_t g_wproj[CH * CH];
__device__ __align__(256) float  g_rw  [C3v + CH];
__device__ __align__(256) int8_t g_q2  [NBH * SEQ * HDIM];
__device__ __align__(256) int8_t g_k2  [NBH * SEQ * HDIM];
__device__ __align__(256) int8_t g_v2t [NBH * HDIM * SEQ];
__device__ __align__(256) int8_t g_x1q [ROWS * CH];
// 0:a_in 1:aq 2:ak 3:av 4:am 5:ap 6:LOG2E*hs*aq*ak 7:am*av 8:1/a_in 9:(am*av)/ap
__device__            float  g_sc[12];

__device__ __forceinline__ float clip8(float x) { return fminf(fmaxf(x, -8.f), 7.f); }
__device__ __forceinline__ int8_t q8(float x) { return (int8_t)__float2int_rn(clip8(x)); }
__device__ __forceinline__ int8_t q8p(float x) { return (int8_t)__float2int_rn(fminf(x, 7.f)); }

__device__ __forceinline__ float pexp2i(int acc, float s6p) {
    return __int_as_float(__float2int_rn(fmaf((float)acc, s6p, 1065353216.0f)));
}

__device__ __forceinline__ void cp16(void* dst, const void* src) {
    uint32_t d = (uint32_t)__cvta_generic_to_shared(dst);
    asm volatile("cp.async.cg.shared.global [%0], [%1], 16;" :: "r"(d), "l"(src));
}
#define CP_COMMIT() asm volatile("cp.async.commit_group;")
#define CP_WAIT1()  asm volatile("cp.async.wait_group 1;")
#define CP_WAIT0()  asm volatile("cp.async.wait_group 0;")

__device__ __forceinline__ uint32_t smem_u32(const void* p) {
    return (uint32_t)__cvta_generic_to_shared(p);
}
__device__ __forceinline__ void ldsm4(uint32_t addr, uint32_t& r0, uint32_t& r1,
                                      uint32_t& r2, uint32_t& r3) {
    asm volatile("ldmatrix.sync.aligned.m8n8.x4.shared.b16 {%0,%1,%2,%3}, [%4];"
                 : "=r"(r0), "=r"(r1), "=r"(r2), "=r"(r3) : "r"(addr));
}
#define MMA_S8(acc, a0, a1, a2, a3, b0, b1) \
    asm volatile("mma.sync.aligned.m16n8k32.row.col.s32.s8.s8.s32 " \
                 "{%0,%1,%2,%3},{%4,%5,%6,%7},{%8,%9},{%0,%1,%2,%3};" \
                 : "+r"((acc)[0]), "+r"((acc)[1]), "+r"((acc)[2]), "+r"((acc)[3]) \
                 : "r"(a0), "r"(a1), "r"(a2), "r"(a3), "r"(b0), "r"(b1))

// ---------------- pre ----------------
__global__ void k_pre(const float* __restrict__ qkv_act_alpha,
                      const float* __restrict__ proj_act_alpha,
                      const float* __restrict__ q_alpha,
                      const float* __restrict__ k_alpha,
                      const float* __restrict__ v_alpha,
                      const float* __restrict__ attn_alpha,
                      const float* __restrict__ qkv_alpha,
                      const float* __restrict__ proj_alpha,
                      const float* __restrict__ qkv_b) {
    __shared__ float sh[256];
    int t = threadIdx.x;
    for (int i = t; i < C3v + CH; i += 256)
        g_rw[i] = 1.0f / (i < C3v ? qkv_alpha[i] : proj_alpha[i - C3v]);
    float s = 0.f;
    for (int i = t; i < CH; i += 256) s += qkv_act_alpha[i];
    sh[t] = s; __syncthreads();
    for (int o = 128; o > 0; o >>= 1) { if (t < o) sh[t] += sh[t + o]; __syncthreads(); }
    float a_in = sh[0] / (float)CH;
    __syncthreads();
    for (int o = t; o < C3v; o += 256)
        g_biasi[o] = (int)truncf(qkv_b[o] / a_in / qkv_alpha[o]);
    s = 0.f;
    for (int i = t; i < CH; i += 256) s += proj_act_alpha[i];
    sh[t] = s; __syncthreads();
    for (int o = 128; o > 0; o >>= 1) { if (t < o) sh[t] += sh[t + o]; __syncthreads(); }
    float ap = sh[0] / (float)CH;
    if (t == 0) {
        float aq = 0.f, ak = 0.f, av = 0.f, am = 0.f;
        for (int i = 0; i < HEADS; i++) { aq += q_alpha[i]; ak += k_alpha[i]; av += v_alpha[i]; am += attn_alpha[i]; }
        aq /= HEADS; ak /= HEADS; av /= HEADS; am /= HEADS;
        g_sc[0] = a_in; g_sc[1] = aq; g_sc[2] = ak; g_sc[3] = av; g_sc[4] = am; g_sc[5] = ap;
        g_sc[6] = 1.4426950408889634f * ((0.125f * aq) * ak);
        g_sc[7] = am * av;
        g_sc[8] = 1.0f / a_in;
        g_sc[9] = (am * av) / ap;
    }
}

// ---------------- fused quantizer: 16 outputs per thread ----------------
constexpr int NG_X0 = ROWS * CH / 16;
constexpr int NG_WQ = C3v * CH / 16;
constexpr int NG_WP = CH * CH / 16;
constexpr int NG_ALL = NG_X0 + NG_WQ + NG_WP;

__device__ __forceinline__ uint32_t pack4(float a, float b, float c, float d) {
    return (uint32_t)(uint8_t)q8(a) | ((uint32_t)(uint8_t)q8(b) << 8) |
           ((uint32_t)(uint8_t)q8(c) << 16) | ((uint32_t)(uint8_t)q8(d) << 24);
}

__global__ void k_quant_all(const float* __restrict__ x0,
                            const float* __restrict__ qkv_w,
                            const float* __restrict__ proj_w) {
    int i = blockIdx.x * blockDim.x + threadIdx.x;
    if (i >= NG_ALL) return;
    const float4* src;
    uint4* dst;
    float r;
    if (i < NG_X0) {
        src = (const float4*)x0 + i * 4;
        dst = (uint4*)g_x0q + i;
        r = g_sc[8];
    } else if (i < NG_X0 + NG_WQ) {
        int k = i - NG_X0;
        src = (const float4*)qkv_w + k * 4;
        dst = (uint4*)g_wqkv + k;
        r = g_rw[k / (CH / 16)];
    } else {
        int k = i - NG_X0 - NG_WQ;
        src = (const float4*)proj_w + k * 4;
        dst = (uint4*)g_wproj + k;
        r = g_rw[C3v + k / (CH / 16)];
    }
    float4 v0 = src[0], v1 = src[1], v2 = src[2], v3 = src[3];
    uint4 o;
    o.x = pack4(v0.x * r, v0.y * r, v0.z * r, v0.w * r);
    o.y = pack4(v1.x * r, v1.y * r, v1.z * r, v1.w * r);
    o.z = pack4(v2.x * r, v2.y * r, v2.z * r, v2.w * r);
    o.w = pack4(v3.x * r, v3.y * r, v3.z * r, v3.w * r);
    *dst = o;
}

// ---------------- QKV GEMM (128x128, 3-stage cp.async, fused norm epilogue) ----------------
constexpr int GSM0 = 128 * 130 * 4;
__global__ void __launch_bounds__(256, 2) gemm_qkv(
        const float* __restrict__ qkv_alpha,
        const float* __restrict__ nqw, const float* __restrict__ nqb,
        const float* __restrict__ nkw, const float* __restrict__ nkb) {
    constexpr int K = 768, BM = 128, BN = 128, BK = 64, NTHR = 256;
    constexpr int WM = 64, WN = 32, MI = 4, NI = 4;
    constexpr int SAS = BK + 16;
    constexpr int NK = K / BK;

    extern __shared__ __align__(16) int8_t dsm[];
    int8_t* As = dsm;
    int8_t* Bs = dsm + 3 * BM * SAS;

    __shared__ float sA[130], sP1[130], sP2[130];
    __shared__ int   sBi[130], coef[64];

    int tid = threadIdx.x;
    int warp = tid >> 5, lane = tid & 31;
    int wr = warp / 4, wc = warp % 4;
    int g = lane >> 2, q4 = lane & 3;
    int rowBase = blockIdx.y * BM;
    int colBase = blockIdx.x * BN;

    if (tid < 128) {
        int col = colBase + tid;
        int d = tid & 63, hs = tid >> 6;
        int idx = d * 2 + hs;
        int branch = col / CH;
        sBi[idx] = g_biasi[col];
        if (branch == 0) {
            float w = nqw[d];
            sA[idx]  = qkv_alpha[col];
            sP1[idx] = nqb[d] / w;
            sP2[idx] = w / g_sc[1];
        } else if (branch == 1) {
            float w = nkw[d];
            sA[idx]  = qkv_alpha[col];
            sP1[idx] = nkb[d] / w;
            sP2[idx] = w / g_sc[2];
        } else {
            sA[idx]  = (g_sc[0] * qkv_alpha[col]) / g_sc[3];
            sP1[idx] = 0.f; sP2[idx] = 0.f;
        }
    }
    if (tid < 64) coef[tid] = 1024 / (tid + 1);

    uint32_t As_base = smem_u32(As);
    uint32_t Bs_base = smem_u32(Bs);
    uint32_t aoff = (uint32_t)(wr * WM + (lane & 15)) * SAS + ((lane >> 4) << 4);
    uint32_t boff = (uint32_t)(wc * WN + (lane & 7) + ((lane >> 4) << 3)) * SAS
                    + (((lane >> 3) & 1) << 4);

    auto load_stage = [&](int st, int k0) {
        #pragma unroll
        for (int idx = tid; idx < BM * BK / 16; idx += NTHR) {
            int r = idx / (BK / 16), seg = idx % (BK / 16);
            cp16(&As[st * BM * SAS + r * SAS + seg * 16],
                 &g_x0q[(long)(rowBase + r) * K + k0 + seg * 16]);
        }
        #pragma unroll
        for (int idx = tid; idx < BN * BK / 16; idx += NTHR) {
            int r = idx / (BK / 16), seg = idx % (BK / 16);
            cp16(&Bs[st * BN * SAS + r * SAS + seg * 16],
                 &g_wqkv[(long)(colBase + r) * K + k0 + seg * 16]);
        }
    };

    int acc[MI][NI][4];
    #pragma unroll
    for (int i = 0; i < MI; i++)
        #pragma unroll
        for (int j = 0; j < NI; j++)
            #pragma unroll
            for (int v = 0; v < 4; v++) acc[i][j][v] = 0;

    load_stage(0, 0); CP_COMMIT();
    load_stage(1, BK); CP_COMMIT();

    for (int it = 0; it < NK; it++) {
        if (it < NK - 1) { CP_WAIT1(); } else { CP_WAIT0(); }
        __syncthreads();
        if (it + 2 < NK) { load_stage((it + 2) % 3, (it + 2) * BK); CP_COMMIT(); }

        int slot = it % 3;
        uint32_t Abase = As_base + (uint32_t)slot * (BM * SAS) + aoff;
        uint32_t Bbase = Bs_base + (uint32_t)slot * (BN * SAS) + boff;

        #pragma unroll
        for (int ks = 0; ks < BK; ks += 32) {
            uint32_t bfr[2][4];
            #pragma unroll
            for (int jj = 0; jj < 2; jj++)
                ldsm4(Bbase + jj * (16 * SAS) + ks,
                      bfr[jj][0], bfr[jj][1], bfr[jj][2], bfr[jj][3]);
            #pragma unroll
            for (int i = 0; i < MI; i++) {
                uint32_t a0, a1, a2, a3;
                ldsm4(Abase + i * (16 * SAS) + ks, a0, a1, a2, a3);
                #pragma unroll
                for (int j = 0; j < NI; j++)
                    MMA_S8(acc[i][j], a0, a1, a2, a3,
                           bfr[j >> 1][(j & 1) * 2], bfr[j >> 1][(j & 1) * 2 + 1]);
            }
        }
    }
    __syncthreads();

    int* sm32 = (int*)dsm;
    int rbL = wr * WM, cbL = wc * WN;
    #pragma unroll
    for (int i = 0; i < MI; i++)
        #pragma unroll
        for (int j = 0; j < NI; j++)
            #pragma unroll
            for (int v = 0; v < 4; v++) {
                int rr = rbL + i * 16 + g + (v >> 1) * 8;
                int cc = cbL + j * 8 + q4 * 2 + (v & 1);
                sm32[rr * 130 + cc + (cc >> 6)] = acc[i][j][v];
            }
    __syncthreads();

    int r = tid >> 1, hs = tid & 1;
    int slice = (colBase >> 6) + hs;
    int branch = slice / HEADS;
    int hh = slice % HEADS;
    int rrG = rowBase + r;
    int bb = rrG >> 10, nn = rrG & 1023;
    int bhh = bb * HEADS + hh;
    const int base = r * 130 + hs * 65;

    if (branch < 2) {
        int m = 0, vv = 0;
        #pragma unroll 8
        for (int d = 0; d < HDIM; d++) {
            int ival = sm32[base + d] + sBi[d * 2 + hs];
            float xf = (float)ival * sA[d * 2 + hs];
            int xi = (int)xf;
            int dd = xi - m;
            m += (dd * coef[d]) >> 10;
            vv += dd * (xi - m);
        }
        float mu = (float)m;
        float invden = 1.0f / (sqrtf((float)vv * 0.015625f) + 1e-5f);
        uint32_t* outp = (uint32_t*)((branch == 0 ? g_q2 : g_k2)
                          + ((long)bhh * SEQ + nn) * HDIM);
        #pragma unroll 4
        for (int dw = 0; dw < 16; dw++) {
            uint32_t pk = 0;
            #pragma unroll
            for (int kk = 0; kk < 4; kk++) {
                int d = dw * 4 + kk;
                int ival = sm32[base + d] + sBi[d * 2 + hs];
                float xf = (float)ival * sA[d * 2 + hs];
                float q1 = (xf - mu) * invden;
                pk |= ((uint32_t)(uint8_t)q8((q1 + sP1[d * 2 + hs]) * sP2[d * 2 + hs]))
                      << (kk * 8);
            }
            outp[dw] = pk;
        }
    } else {
        int8_t* outv = g_v2t + (long)bhh * HDIM * SEQ + nn;
        #pragma unroll 8
        for (int d = 0; d < HDIM; d++) {
            int ival = sm32[base + d] + sBi[d * 2 + hs];
            outv[d * SEQ] = q8((float)ival * sA[d * 2 + hs]);
        }
    }
}

// ---------------- proj GEMM (128x64, 3-stage cp.async, 3 CTAs/SM) ----------------
constexpr int GSM1 = 3 * (128 + 64) * 80;   // 46080
__global__ void __launch_bounds__(256, 3) gemm_proj(float* __restrict__ outf,
        const float* __restrict__ e1, const float* __restrict__ e2) {
    constexpr int K = 768, BM = 128, BN = 64, BK = 64, NTHR = 256;
    constexpr int WM = 64, WN = 16, MI = 4, NI = 2;
    constexpr int SAS = BK + 16;
    constexpr int NK = K / BK;

    extern __shared__ __align__(16) int8_t dsm[];
    int8_t* As = dsm;
    int8_t* Bs = dsm + 3 * BM * SAS;

    __shared__ float sA[64], sP1[64];

    int tid = threadIdx.x;
    int warp = tid >> 5, lane = tid & 31;
    int wr = warp / 4, wc = warp % 4;
    int g = lane >> 2, q4 = lane & 3;
    int rowBase = blockIdx.y * BM;
    int colBase = blockIdx.x * BN;

    if (tid < BN) {
        int cc = colBase + tid;
        sA[tid]  = e1[cc] * g_sc[5];
        sP1[tid] = e2[cc];
    }

    uint32_t As_base = smem_u32(As);
    uint32_t Bs_base = smem_u32(Bs);
    uint32_t aoff = (uint32_t)(wr * WM + (lane & 15)) * SAS + ((lane >> 4) << 4);
    uint32_t boff = (uint32_t)(wc * WN + (lane & 7) + ((lane >> 4) << 3)) * SAS
                    + (((lane >> 3) & 1) << 4);

    auto load_stage = [&](int st, int k0) {
        #pragma unroll
        for (int idx = tid; idx < BM * BK / 16; idx += NTHR) {
            int r = idx / (BK / 16), seg = idx % (BK / 16);
            cp16(&As[st * BM * SAS + r * SAS + seg * 16],
                 &g_x1q[(long)(rowBase + r) * K + k0 + seg * 16]);
        }
        #pragma unroll
        for (int idx = tid; idx < BN * BK / 16; idx += NTHR) {
            int r = idx / (BK / 16), seg = idx % (BK / 16);
            cp16(&Bs[st * BN * SAS + r * SAS + seg * 16],
                 &g_wproj[(long)(colBase + r) * K + k0 + seg * 16]);
        }
    };

    int acc[MI][NI][4];
    #pragma unroll
    for (int i = 0; i < MI; i++)
        #pragma unroll
        for (int j = 0; j < NI; j++)
            #pragma unroll
            for (int v = 0; v < 4; v++) acc[i][j][v] = 0;

    load_stage(0, 0); CP_COMMIT();
    load_stage(1, BK); CP_COMMIT();

    for (int it = 0; it < NK; it++) {
        if (it < NK - 1) { CP_WAIT1(); } else { CP_WAIT0(); }
        __syncthreads();
        if (it + 2 < NK) { load_stage((it + 2) % 3, (it + 2) * BK); CP_COMMIT(); }

        int slot = it % 3;
        uint32_t Abase = As_base + (uint32_t)slot * (BM * SAS) + aoff;
        uint32_t Bbase = Bs_base + (uint32_t)slot * (BN * SAS) + boff;

        #pragma unroll
        for (int ks = 0; ks < BK; ks += 32) {
            uint32_t bfr[4];
            ldsm4(Bbase + ks, bfr[0], bfr[1], bfr[2], bfr[3]);
            #pragma unroll
            for (int i = 0; i < MI; i++) {
                uint32_t a0, a1, a2, a3;
                ldsm4(Abase + i * (16 * SAS) + ks, a0, a1, a2, a3);
                MMA_S8(acc[i][0], a0, a1, a2, a3, bfr[0], bfr[1]);
                MMA_S8(acc[i][1], a0, a1, a2, a3, bfr[2], bfr[3]);
            }
        }
    }
    __syncthreads();

    int rb = rowBase + wr * WM;
    int cb = wc * WN;
    #pragma unroll
    for (int i = 0; i < MI; i++)
        #pragma unroll
        for (int j = 0; j < NI; j++)
            #pragma unroll
            for (int v = 0; v < 4; v++) {
                int rr = rb + i * 16 + g + (v >> 1) * 8;
                int ccl = cb + j * 8 + q4 * 2 + (v & 1);
                outf[(long)rr * CH + colBase + ccl] =
                    (float)acc[i][j][v] * sA[ccl] + sP1[ccl];
            }
}

// ---------------- fused flash attention: quarter-streamed K/V, 3 CTAs/SM ----------------
constexpr int ATT_B0 = 0;
constexpr int ATT_B1 = 20480;
constexpr int ATT_A  = 40960;
constexpr int ATT_Q  = 57600;
constexpr int ATT_S  = 58880;
constexpr int SMEM_ATT = 58944;

__global__ void __launch_bounds__(256, 3) k_attn_fused() {
    extern __shared__ __align__(16) int8_t sh[];
    int8_t* B0  = sh + ATT_B0;
    int8_t* B1  = sh + ATT_B1;
    int8_t* Asm = sh + ATT_A;
    int8_t* Qsm = sh + ATT_Q;
    float*  rs  = (float*)(sh + ATT_S);

    int bh = blockIdx.y;
    int h = bh % HEADS, b = bh / HEADS;
    int qBase = blockIdx.x * 16;
    int tid = threadIdx.x, w = tid >> 5, lane = tid & 31;
    int g = lane >> 2, q4 = lane & 3;

    const int8_t* Qg = g_q2 + ((long)bh * SEQ + qBase) * HDIM;
    const int8_t* Kg = g_k2 + (long)bh * SEQ * HDIM;
    const int8_t* Vg = g_v2t + (long)bh * HDIM * SEQ;

    if (tid < 64) {
        int r = tid >> 2, s = tid & 3;
        cp16(&Qsm[r * 80 + s * 16], &Qg[r * 64 + s * 16]);
    }
    #pragma unroll
    for (int t2 = 0; t2 < 4; t2++) {
        int idx = tid + t2 * 256;
        int r = idx >> 2, s = idx & 3;
        cp16(&B0[r * 80 + s * 16], &Kg[r * 64 + s * 16]);
    }
    CP_COMMIT();
    #pragma unroll
    for (int t2 = 0; t2 < 4; t2++) {
        int idx = tid + t2 * 256;
        int r = idx >> 2, s = idx & 3;
        cp16(&B1[r * 80 + s * 16], &Kg[(256 + r) * 64 + s * 16]);
    }
    CP_COMMIT();
    if (tid < 16) rs[tid] = 0.f;
    CP_WAIT1();
    __syncthreads();

    uint32_t B0u = smem_u32(B0), B1u = smem_u32(B1);
    uint32_t Qu  = smem_u32(Qsm);
    uint32_t aoffQ = (uint32_t)(lane & 15) * 80 + ((lane >> 4) << 4);
    uint32_t kfoff = (uint32_t)(w * 32 + (lane & 7) + ((lane >> 4) << 3)) * 80
                     + (((lane >> 3) & 1) << 4);

    int acc[16][4];
    #pragma unroll
    for (int j = 0; j < 16; j++)
        #pragma unroll
        for (int v = 0; v < 4; v++) acc[j][v] = 0;

    #pragma unroll
    for (int qi = 0; qi < 4; qi++) {
        uint32_t bufU = (qi & 1) ? B1u : B0u;
        int8_t*  buf  = (qi & 1) ? B1 : B0;
        #pragma unroll
        for (int ks2 = 0; ks2 < 2; ks2++) {
            uint32_t a0, a1, a2, a3;
            ldsm4(Qu + aoffQ + ks2 * 32, a0, a1, a2, a3);
            #pragma unroll
            for (int p = 0; p < 2; p++) {
                uint32_t b0, b1, b2, b3;
                ldsm4(bufU + kfoff + (uint32_t)p * (16 * 80) + ks2 * 32, b0, b1, b2, b3);
                MMA_S8(acc[qi * 4 + 2 * p],     a0, a1, a2, a3, b0, b1);
                MMA_S8(acc[qi * 4 + 2 * p + 1], a0, a1, a2, a3, b2, b3);
            }
        }
        __syncthreads();
        if (qi < 2) {
            #pragma unroll
            for (int t2 = 0; t2 < 4; t2++) {
                int idx = tid + t2 * 256;
                int r = idx >> 2, s = idx & 3;
                cp16(&buf[r * 80 + s * 16], &Kg[((qi + 2) * 256 + r) * 64 + s * 16]);
            }
            CP_COMMIT();
            CP_WAIT1();
            __syncthreads();
        } else if (qi == 2) {
            #pragma unroll
            for (int t2 = 0; t2 < 4; t2++) {
                int idx = tid + t2 * 256;
                int d = idx >> 4, s = idx & 15;
                cp16(&buf[d * 272 + s * 16], &Vg[d * 1024 + s * 16]);
            }
            CP_COMMIT();
            CP_WAIT1();
            __syncthreads();
        } else {
            #pragma unroll
            for (int t2 = 0; t2 < 4; t2++) {
                int idx = tid + t2 * 256;
                int d = idx >> 4, s = idx & 15;
                cp16(&buf[d * 272 + s * 16], &Vg[d * 1024 + 256 + s * 16]);
            }
            CP_COMMIT();
        }
    }

    float s6p = g_sc[6] * 8388608.0f;
    float sum0 = 0.f, sum1 = 0.f;
    #pragma unroll
    for (int j = 0; j < 16; j++) {
        float p0 = pexp2i(acc[j][0], s6p);
        float p1 = pexp2i(acc[j][1], s6p);
        float p2 = pexp2i(acc[j][2], s6p);
        float p3 = pexp2i(acc[j][3], s6p);
        acc[j][0] = __float_as_int(p0); acc[j][1] = __float_as_int(p1);
        acc[j][2] = __float_as_int(p2); acc[j][3] = __float_as_int(p3);
        sum0 += p0 + p1;
        sum1 += p2 + p3;
    }
    sum0 += __shfl_xor_sync(0xffffffffu, sum0, 1);
    sum0 += __shfl_xor_sync(0xffffffffu, sum0, 2);
    sum1 += __shfl_xor_sync(0xffffffffu, sum1, 1);
    sum1 += __shfl_xor_sync(0xffffffffu, sum1, 2);
    if (q4 == 0) {
        atomicAdd(&rs[g], sum0);
        atomicAdd(&rs[g + 8], sum1);
    }
    __syncthreads();
    if (tid < 16) rs[tid] = 1.0f / (rs[tid] * g_sc[4]);
    __syncthreads();

    float iv0 = rs[g], iv1 = rs[g + 8];
    #pragma unroll
    for (int j = 0; j < 16; j++) {
        int col = (j >> 2) * 256 + w * 32 + (j & 3) * 8 + q4 * 2;
        uint8_t v0 = (uint8_t)q8p(__int_as_float(acc[j][0]) * iv0);
        uint8_t v1 = (uint8_t)q8p(__int_as_float(acc[j][1]) * iv0);
        *(uint16_t*)&Asm[g * 1040 + col] = (uint16_t)v0 | ((uint16_t)v1 << 8);
        uint8_t v2 = (uint8_t)q8p(__int_as_float(acc[j][2]) * iv1);
        uint8_t v3 = (uint8_t)q8p(__int_as_float(acc[j][3]) * iv1);
        *(uint16_t*)&Asm[(g + 8) * 1040 + col] = (uint16_t)v2 | ((uint16_t)v3 << 8);
    }
    CP_WAIT1();
    __syncthreads();

    uint32_t Aoff  = smem_u32(Asm) + (uint32_t)(lane & 15) * 1040 + ((lane >> 4) << 4);
    uint32_t Vfoff = (uint32_t)(w * 8 + (lane & 7)) * 272 + ((lane >> 3) << 4);

    int pv[4] = {0, 0, 0, 0};
    #pragma unroll
    for (int qv = 0; qv < 4; qv++) {
        uint32_t bufU = (qv & 1) ? B1u : B0u;
        int8_t*  buf  = (qv & 1) ? B1 : B0;
        uint32_t Abase = Aoff + (uint32_t)qv * 256;
        #pragma unroll
        for (int ksl = 0; ksl < 256; ksl += 64) {
            uint32_t va, vb, vc, vd;
            ldsm4(bufU + Vfoff + ksl, va, vb, vc, vd);
            uint32_t a0, a1, a2, a3;
            ldsm4(Abase + ksl, a0, a1, a2, a3);
            MMA_S8(pv, a0, a1, a2, a3, va, vb);
            ldsm4(Abase + ksl + 32, a0, a1, a2, a3);
            MMA_S8(pv, a0, a1, a2, a3, vc, vd);
        }
        if (qv < 2) {
            __syncthreads();
            #pragma unroll
            for (int t2 = 0; t2 < 4; t2++) {
                int idx = tid + t2 * 256;
                int d = idx >> 4, s = idx & 15;
                cp16(&buf[d * 272 + s * 16], &Vg[d * 1024 + (qv + 2) * 256 + s * 16]);
            }
            CP_COMMIT();
            CP_WAIT1();
            __syncthreads();
        } else if (qv == 2) {
            CP_WAIT0();
            __syncthreads();
        }
    }

    float r9 = g_sc[9];
    long base0 = ((long)(b * SEQ + qBase + g)) * CH + h * HDIM + w * 8 + q4 * 2;
    uint16_t pA = (uint16_t)(uint8_t)q8((float)pv[0] * r9)
                | ((uint16_t)(uint8_t)q8((float)pv[1] * r9) << 8);
    *(uint16_t*)&g_x1q[base0] = pA;
    uint16_t pB = (uint16_t)(uint8_t)q8((float)pv[2] * r9)
                | ((uint16_t)(uint8_t)q8((float)pv[3] * r9) << 8);
    *(uint16_t*)&g_x1q[base0 + 8L * CH] = pB;
}

// ---------------- launcher (serial, monolithic) ----------------
extern "C" void kernel_launch(void* const* d_in, const int* in_sizes, int n_in,
                              void* d_out, int out_size) {
    const float* x0             = (const float*)d_in[0];
    const float* qkv_w          = (const float*)d_in[1];
    const float* qkv_b          = (const float*)d_in[2];
    const float* qkv_alpha      = (const float*)d_in[3];
    const float* qkv_act_alpha  = (const float*)d_in[4];
    const float* proj_w         = (const float*)d_in[5];
    const float* proj_b         = (const float*)d_in[6];
    const float* proj_alpha     = (const float*)d_in[7];
    const float* proj_act_alpha = (const float*)d_in[8];
    const float* norm_q_w       = (const float*)d_in[9];
    const float* norm_q_b       = (const float*)d_in[10];
    const float* norm_k_w       = (const float*)d_in[11];
    const float* norm_k_b       = (const float*)d_in[12];
    const float* q_alpha        = (const float*)d_in[13];
    const float* k_alpha        = (const float*)d_in[14];
    const float* v_alpha        = (const float*)d_in[15];
    const float* attn_alpha     = (const float*)d_in[16];
    float* out = (float*)d_out;

    cudaFuncSetAttribute(k_attn_fused, cudaFuncAttributeMaxDynamicSharedMemorySize, SMEM_ATT);
    cudaFuncSetAttribute(gemm_qkv, cudaFuncAttributeMaxDynamicSharedMemorySize, GSM0);
    cudaFuncSetAttribute(gemm_proj, cudaFuncAttributeMaxDynamicSharedMemorySize, GSM1);

    // 1
    k_pre<<<1, 256>>>(qkv_act_alpha, proj_act_alpha, q_alpha, k_alpha, v_alpha,
                      attn_alpha, qkv_alpha, proj_alpha, qkv_b);
    // 2: fused quantizer, 16B/thread
    k_quant_all<<<(NG_ALL + 255) / 256, 256>>>(x0, qkv_w, proj_w);
    // 3: QKV GEMM + fused norm (576 CTAs)
    gemm_qkv<<<dim3(C3v / 128, ROWS / 128, 1), 256, GSM0>>>(
        qkv_alpha, norm_q_w, norm_q_b, norm_k_w, norm_k_b);
    // 4: fused attention (3 CTAs/SM)
    k_attn_fused<<<dim3(SEQ / 16, NBH), 256, SMEM_ATT>>>();
    // 5: projection GEMM (384 CTAs, 3 CTAs/SM -> single wave)
    gemm_proj<<<dim3(CH / 64, ROWS / 128, 1), 256, GSM1>>>(out, proj_alpha, proj_b);
}

// round 16
// speedup vs baseline: 1.0019x; 1.0018x over previous
#include <cuda_runtime.h>
#include <stdint.h>

// ---------------- problem constants ----------------
constexpr int BATCH = 4, SEQ = 1024, CH = 768, HEADS = 12, HDIM = 64;
constexpr int ROWS = BATCH * SEQ;   // 4096
constexpr int C3v  = 3 * CH;        // 2304
constexpr int NBH  = BATCH * HEADS; // 48

// ---------------- scratch ----------------
__device__ __align__(256) int8_t g_x0q [ROWS * CH];
__device__ __align__(256) int8_t g_wqkv[C3v * CH];
__device__            int    g_biasi[C3v];
__device__ __align__(256) int8_t g_wproj[CH * CH];
__device__ __align__(256) float  g_rw  [C3v + CH];
__device__ __align__(256) int8_t g_q2  [NBH * SEQ * HDIM];
__device__ __align__(256) int8_t g_k2  [NBH * SEQ * HDIM];
__device__ __align__(256) int8_t g_v2t [NBH * HDIM * SEQ];
__device__ __align__(256) int8_t g_x1q [ROWS * CH];
// 0:a_in 1:aq 2:ak 3:av 4:am 5:ap 6:LOG2E*hs*aq*ak 7:am*av 8:1/a_in 9:(am*av)/ap
__device__            float  g_sc[12];

__device__ __forceinline__ float clip8(float x) { return fminf(fmaxf(x, -8.f), 7.f); }
__device__ __forceinline__ int8_t q8(float x) { return (int8_t)__float2int_rn(clip8(x)); }
__device__ __forceinline__ int8_t q8p(float x) { return (int8_t)__float2int_rn(fminf(x, 7.f)); }

__device__ __forceinline__ float pexp2i(int acc, float s6p) {
    return __int_as_float(__float2int_rn(fmaf((float)acc, s6p, 1065353216.0f)));
}

__device__ __forceinline__ void cp16(void* dst, const void* src) {
    uint32_t d = (uint32_t)__cvta_generic_to_shared(dst);
    asm volatile("cp.async.cg.shared.global [%0], [%1], 16;" :: "r"(d), "l"(src));
}
#define CP_COMMIT() asm volatile("cp.async.commit_group;")
#define CP_WAIT1()  asm volatile("cp.async.wait_group 1;")
#define CP_WAIT0()  asm volatile("cp.async.wait_group 0;")

__device__ __forceinline__ uint32_t smem_u32(const void* p) {
    return (uint32_t)__cvta_generic_to_shared(p);
}
__device__ __forceinline__ void ldsm4(uint32_t addr, uint32_t& r0, uint32_t& r1,
                                      uint32_t& r2, uint32_t& r3) {
    asm volatile("ldmatrix.sync.aligned.m8n8.x4.shared.b16 {%0,%1,%2,%3}, [%4];"
                 : "=r"(r0), "=r"(r1), "=r"(r2), "=r"(r3) : "r"(addr));
}
#define MMA_S8(acc, a0, a1, a2, a3, b0, b1) \
    asm volatile("mma.sync.aligned.m16n8k32.row.col.s32.s8.s8.s32 " \
                 "{%0,%1,%2,%3},{%4,%5,%6,%7},{%8,%9},{%0,%1,%2,%3};" \
                 : "+r"((acc)[0]), "+r"((acc)[1]), "+r"((acc)[2]), "+r"((acc)[3]) \
                 : "r"(a0), "r"(a1), "r"(a2), "r"(a3), "r"(b0), "r"(b1))

// ---------------- pre ----------------
__global__ void k_pre(const float* __restrict__ qkv_act_alpha,
                      const float* __restrict__ proj_act_alpha,
                      const float* __restrict__ q_alpha,
                      const float* __restrict__ k_alpha,
                      const float* __restrict__ v_alpha,
                      const float* __restrict__ attn_alpha,
                      const float* __restrict__ qkv_alpha,
                      const float* __restrict__ proj_alpha,
                      const float* __restrict__ qkv_b) {
    __shared__ float sh[256];
    int t = threadIdx.x;
    for (int i = t; i < C3v + CH; i += 256)
        g_rw[i] = 1.0f / (i < C3v ? qkv_alpha[i] : proj_alpha[i - C3v]);
    float s = 0.f;
    for (int i = t; i < CH; i += 256) s += qkv_act_alpha[i];
    sh[t] = s; __syncthreads();
    for (int o = 128; o > 0; o >>= 1) { if (t < o) sh[t] += sh[t + o]; __syncthreads(); }
    float a_in = sh[0] / (float)CH;
    __syncthreads();
    for (int o = t; o < C3v; o += 256)
        g_biasi[o] = (int)truncf(qkv_b[o] / a_in / qkv_alpha[o]);
    s = 0.f;
    for (int i = t; i < CH; i += 256) s += proj_act_alpha[i];
    sh[t] = s; __syncthreads();
    for (int o = 128; o > 0; o >>= 1) { if (t < o) sh[t] += sh[t + o]; __syncthreads(); }
    float ap = sh[0] / (float)CH;
    if (t == 0) {
        float aq = 0.f, ak = 0.f, av = 0.f, am = 0.f;
        for (int i = 0; i < HEADS; i++) { aq += q_alpha[i]; ak += k_alpha[i]; av += v_alpha[i]; am += attn_alpha[i]; }
        aq /= HEADS; ak /= HEADS; av /= HEADS; am /= HEADS;
        g_sc[0] = a_in; g_sc[1] = aq; g_sc[2] = ak; g_sc[3] = av; g_sc[4] = am; g_sc[5] = ap;
        g_sc[6] = 1.4426950408889634f * ((0.125f * aq) * ak);
        g_sc[7] = am * av;
        g_sc[8] = 1.0f / a_in;
        g_sc[9] = (am * av) / ap;
    }
}

// ---------------- fused quantizer: 16 outputs per thread ----------------
constexpr int NG_X0 = ROWS * CH / 16;
constexpr int NG_WQ = C3v * CH / 16;
constexpr int NG_WP = CH * CH / 16;
constexpr int NG_ALL = NG_X0 + NG_WQ + NG_WP;

__device__ __forceinline__ uint32_t pack4(float a, float b, float c, float d) {
    return (uint32_t)(uint8_t)q8(a) | ((uint32_t)(uint8_t)q8(b) << 8) |
           ((uint32_t)(uint8_t)q8(c) << 16) | ((uint32_t)(uint8_t)q8(d) << 24);
}

__global__ void k_quant_all(const float* __restrict__ x0,
                            const float* __restrict__ qkv_w,
                            const float* __restrict__ proj_w) {
    int i = blockIdx.x * blockDim.x + threadIdx.x;
    if (i >= NG_ALL) return;
    const float4* src;
    uint4* dst;
    float r;
    if (i < NG_X0) {
        src = (const float4*)x0 + i * 4;
        dst = (uint4*)g_x0q + i;
        r = g_sc[8];
    } else if (i < NG_X0 + NG_WQ) {
        int k = i - NG_X0;
        src = (const float4*)qkv_w + k * 4;
        dst = (uint4*)g_wqkv + k;
        r = g_rw[k / (CH / 16)];
    } else {
        int k = i - NG_X0 - NG_WQ;
        src = (const float4*)proj_w + k * 4;
        dst = (uint4*)g_wproj + k;
        r = g_rw[C3v + k / (CH / 16)];
    }
    float4 v0 = src[0], v1 = src[1], v2 = src[2], v3 = src[3];
    uint4 o;
    o.x = pack4(v0.x * r, v0.y * r, v0.z * r, v0.w * r);
    o.y = pack4(v1.x * r, v1.y * r, v1.z * r, v1.w * r);
    o.z = pack4(v2.x * r, v2.y * r, v2.z * r, v2.w * r);
    o.w = pack4(v3.x * r, v3.y * r, v3.z * r, v3.w * r);
    *dst = o;
}

// ---------------- QKV GEMM (128x128, 3-stage cp.async, fused norm epilogue) ----------------
constexpr int GSM0 = 128 * 130 * 4;
__global__ void __launch_bounds__(256, 2) gemm_qkv(
        const float* __restrict__ qkv_alpha,
        const float* __restrict__ nqw, const float* __restrict__ nqb,
        const float* __restrict__ nkw, const float* __restrict__ nkb) {
    constexpr int K = 768, BM = 128, BN = 128, BK = 64, NTHR = 256;
    constexpr int WM = 64, WN = 32, MI = 4, NI = 4;
    constexpr int SAS = BK + 16;
    constexpr int NK = K / BK;

    extern __shared__ __align__(16) int8_t dsm[];
    int8_t* As = dsm;
    int8_t* Bs = dsm + 3 * BM * SAS;

    __shared__ float sA[130], sP1[130], sP2[130];
    __shared__ int   sBi[130], coef[64];

    int tid = threadIdx.x;
    int warp = tid >> 5, lane = tid & 31;
    int wr = warp / 4, wc = warp % 4;
    int g = lane >> 2, q4 = lane & 3;
    int rowBase = blockIdx.y * BM;
    int colBase = blockIdx.x * BN;

    if (tid < 128) {
        int col = colBase + tid;
        int d = tid & 63, hs = tid >> 6;
        int idx = d * 2 + hs;
        int branch = col / CH;
        sBi[idx] = g_biasi[col];
        if (branch == 0) {
            float w = nqw[d];
            sA[idx]  = qkv_alpha[col];
            sP1[idx] = nqb[d] / w;
            sP2[idx] = w / g_sc[1];
        } else if (branch == 1) {
            float w = nkw[d];
            sA[idx]  = qkv_alpha[col];
            sP1[idx] = nkb[d] / w;
            sP2[idx] = w / g_sc[2];
        } else {
            sA[idx]  = (g_sc[0] * qkv_alpha[col]) / g_sc[3];
            sP1[idx] = 0.f; sP2[idx] = 0.f;
        }
    }
    if (tid < 64) coef[tid] = 1024 / (tid + 1);

    uint32_t As_base = smem_u32(As);
    uint32_t Bs_base = smem_u32(Bs);
    uint32_t aoff = (uint32_t)(wr * WM + (lane & 15)) * SAS + ((lane >> 4) << 4);
    uint32_t boff = (uint32_t)(wc * WN + (lane & 7) + ((lane >> 4) << 3)) * SAS
                    + (((lane >> 3) & 1) << 4);

    auto load_stage = [&](int st, int k0) {
        #pragma unroll
        for (int idx = tid; idx < BM * BK / 16; idx += NTHR) {
            int r = idx / (BK / 16), seg = idx % (BK / 16);
            cp16(&As[st * BM * SAS + r * SAS + seg * 16],
                 &g_x0q[(long)(rowBase + r) * K + k0 + seg * 16]);
        }
        #pragma unroll
        for (int idx = tid; idx < BN * BK / 16; idx += NTHR) {
            int r = idx / (BK / 16), seg = idx % (BK / 16);
            cp16(&Bs[st * BN * SAS + r * SAS + seg * 16],
                 &g_wqkv[(long)(colBase + r) * K + k0 + seg * 16]);
        }
    };

    int acc[MI][NI][4];
    #pragma unroll
    for (int i = 0; i < MI; i++)
        #pragma unroll
        for (int j = 0; j < NI; j++)
            #pragma unroll
            for (int v = 0; v < 4; v++) acc[i][j][v] = 0;

    load_stage(0, 0); CP_COMMIT();
    load_stage(1, BK); CP_COMMIT();

    for (int it = 0; it < NK; it++) {
        if (it < NK - 1) { CP_WAIT1(); } else { CP_WAIT0(); }
        __syncthreads();
        if (it + 2 < NK) { load_stage((it + 2) % 3, (it + 2) * BK); CP_COMMIT(); }

        int slot = it % 3;
        uint32_t Abase = As_base + (uint32_t)slot * (BM * SAS) + aoff;
        uint32_t Bbase = Bs_base + (uint32_t)slot * (BN * SAS) + boff;

        #pragma unroll
        for (int ks = 0; ks < BK; ks += 32) {
            uint32_t bfr[2][4];
            #pragma unroll
            for (int jj = 0; jj < 2; jj++)
                ldsm4(Bbase + jj * (16 * SAS) + ks,
                      bfr[jj][0], bfr[jj][1], bfr[jj][2], bfr[jj][3]);
            #pragma unroll
            for (int i = 0; i < MI; i++) {
                uint32_t a0, a1, a2, a3;
                ldsm4(Abase + i * (16 * SAS) + ks, a0, a1, a2, a3);
                #pragma unroll
                for (int j = 0; j < NI; j++)
                    MMA_S8(acc[i][j], a0, a1, a2, a3,
                           bfr[j >> 1][(j & 1) * 2], bfr[j >> 1][(j & 1) * 2 + 1]);
            }
        }
    }
    __syncthreads();

    int* sm32 = (int*)dsm;
    int rbL = wr * WM, cbL = wc * WN;
    #pragma unroll
    for (int i = 0; i < MI; i++)
        #pragma unroll
        for (int j = 0; j < NI; j++)
            #pragma unroll
            for (int v = 0; v < 4; v++) {
                int rr = rbL + i * 16 + g + (v >> 1) * 8;
                int cc = cbL + j * 8 + q4 * 2 + (v & 1);
                sm32[rr * 130 + cc + (cc >> 6)] = acc[i][j][v];
            }
    __syncthreads();

    int r = tid >> 1, hs = tid & 1;
    int slice = (colBase >> 6) + hs;
    int branch = slice / HEADS;
    int hh = slice % HEADS;
    int rrG = rowBase + r;
    int bb = rrG >> 10, nn = rrG & 1023;
    int bhh = bb * HEADS + hh;
    const int base = r * 130 + hs * 65;

    if (branch < 2) {
        int m = 0, vv = 0;
        #pragma unroll 8
        for (int d = 0; d < HDIM; d++) {
            int ival = sm32[base + d] + sBi[d * 2 + hs];
            float xf = (float)ival * sA[d * 2 + hs];
            int xi = (int)xf;
            int dd = xi - m;
            m += (dd * coef[d]) >> 10;
            vv += dd * (xi - m);
        }
        float mu = (float)m;
        float invden = 1.0f / (sqrtf((float)vv * 0.015625f) + 1e-5f);
        uint32_t* outp = (uint32_t*)((branch == 0 ? g_q2 : g_k2)
                          + ((long)bhh * SEQ + nn) * HDIM);
        #pragma unroll 4
        for (int dw = 0; dw < 16; dw++) {
            uint32_t pk = 0;
            #pragma unroll
            for (int kk = 0; kk < 4; kk++) {
                int d = dw * 4 + kk;
                int ival = sm32[base + d] + sBi[d * 2 + hs];
                float xf = (float)ival * sA[d * 2 + hs];
                float q1 = (xf - mu) * invden;
                pk |= ((uint32_t)(uint8_t)q8((q1 + sP1[d * 2 + hs]) * sP2[d * 2 + hs]))
                      << (kk * 8);
            }
            outp[dw] = pk;
        }
    } else {
        int8_t* outv = g_v2t + (long)bhh * HDIM * SEQ + nn;
        #pragma unroll 8
        for (int d = 0; d < HDIM; d++) {
            int ival = sm32[base + d] + sBi[d * 2 + hs];
            outv[d * SEQ] = q8((float)ival * sA[d * 2 + hs]);
        }
    }
}

// ---------------- proj GEMM (128x64, 3-stage cp.async, 3 CTAs/SM) ----------------
constexpr int GSM1 = 3 * (128 + 64) * 80;   // 46080
__global__ void __launch_bounds__(256, 3) gemm_proj(float* __restrict__ outf,
        const float* __restrict__ e1, const float* __restrict__ e2) {
    constexpr int K = 768, BM = 128, BN = 64, BK = 64, NTHR = 256;
    constexpr int WM = 64, WN = 16, MI = 4, NI = 2;
    constexpr int SAS = BK + 16;
    constexpr int NK = K / BK;

    extern __shared__ __align__(16) int8_t dsm[];
    int8_t* As = dsm;
    int8_t* Bs = dsm + 3 * BM * SAS;

    __shared__ float sA[64], sP1[64];

    int tid = threadIdx.x;
    int warp = tid >> 5, lane = tid & 31;
    int wr = warp / 4, wc = warp % 4;
    int g = lane >> 2, q4 = lane & 3;
    int rowBase = blockIdx.y * BM;
    int colBase = blockIdx.x * BN;

    if (tid < BN) {
        int cc = colBase + tid;
        sA[tid]  = e1[cc] * g_sc[5];
        sP1[tid] = e2[cc];
    }

    uint32_t As_base = smem_u32(As);
    uint32_t Bs_base = smem_u32(Bs);
    uint32_t aoff = (uint32_t)(wr * WM + (lane & 15)) * SAS + ((lane >> 4) << 4);
    uint32_t boff = (uint32_t)(wc * WN + (lane & 7) + ((lane >> 4) << 3)) * SAS
                    + (((lane >> 3) & 1) << 4);

    auto load_stage = [&](int st, int k0) {
        #pragma unroll
        for (int idx = tid; idx < BM * BK / 16; idx += NTHR) {
            int r = idx / (BK / 16), seg = idx % (BK / 16);
            cp16(&As[st * BM * SAS + r * SAS + seg * 16],
                 &g_x1q[(long)(rowBase + r) * K + k0 + seg * 16]);
        }
        #pragma unroll
        for (int idx = tid; idx < BN * BK / 16; idx += NTHR) {
            int r = idx / (BK / 16), seg = idx % (BK / 16);
            cp16(&Bs[st * BN * SAS + r * SAS + seg * 16],
                 &g_wproj[(long)(colBase + r) * K + k0 + seg * 16]);
        }
    };

    int acc[MI][NI][4];
    #pragma unroll
    for (int i = 0; i < MI; i++)
        #pragma unroll
        for (int j = 0; j < NI; j++)
            #pragma unroll
            for (int v = 0; v < 4; v++) acc[i][j][v] = 0;

    load_stage(0, 0); CP_COMMIT();
    load_stage(1, BK); CP_COMMIT();

    for (int it = 0; it < NK; it++) {
        if (it < NK - 1) { CP_WAIT1(); } else { CP_WAIT0(); }
        __syncthreads();
        if (it + 2 < NK) { load_stage((it + 2) % 3, (it + 2) * BK); CP_COMMIT(); }

        int slot = it % 3;
        uint32_t Abase = As_base + (uint32_t)slot * (BM * SAS) + aoff;
        uint32_t Bbase = Bs_base + (uint32_t)slot * (BN * SAS) + boff;

        #pragma unroll
        for (int ks = 0; ks < BK; ks += 32) {
            uint32_t bfr[4];
            ldsm4(Bbase + ks, bfr[0], bfr[1], bfr[2], bfr[3]);
            #pragma unroll
            for (int i = 0; i < MI; i++) {
                uint32_t a0, a1, a2, a3;
                ldsm4(Abase + i * (16 * SAS) + ks, a0, a1, a2, a3);
                MMA_S8(acc[i][0], a0, a1, a2, a3, bfr[0], bfr[1]);
                MMA_S8(acc[i][1], a0, a1, a2, a3, bfr[2], bfr[3]);
            }
        }
    }
    __syncthreads();

    int rb = rowBase + wr * WM;
    int cb = wc * WN;
    #pragma unroll
    for (int i = 0; i < MI; i++)
        #pragma unroll
        for (int j = 0; j < NI; j++)
            #pragma unroll
            for (int v = 0; v < 4; v++) {
                int rr = rb + i * 16 + g + (v >> 1) * 8;
                int ccl = cb + j * 8 + q4 * 2 + (v & 1);
                outf[(long)rr * CH + colBase + ccl] =
                    (float)acc[i][j][v] * sA[ccl] + sP1[ccl];
            }
}

// ---------------- fused flash attention: quarter-streamed K/V, 3 CTAs/SM ----------------
constexpr int ATT_B0 = 0;
constexpr int ATT_B1 = 20480;
constexpr int ATT_A  = 40960;
constexpr int ATT_Q  = 57600;
constexpr int ATT_S  = 58880;
constexpr int SMEM_ATT = 58944;

__global__ void __launch_bounds__(256, 3) k_attn_fused() {
    extern __shared__ __align__(16) int8_t sh[];
    int8_t* B0  = sh + ATT_B0;
    int8_t* B1  = sh + ATT_B1;
    int8_t* Asm = sh + ATT_A;
    int8_t* Qsm = sh + ATT_Q;
    float*  rs  = (float*)(sh + ATT_S);

    int bh = blockIdx.y;
    int h = bh % HEADS, b = bh / HEADS;
    int qBase = blockIdx.x * 16;
    int tid = threadIdx.x, w = tid >> 5, lane = tid & 31;
    int g = lane >> 2, q4 = lane & 3;

    const int8_t* Qg = g_q2 + ((long)bh * SEQ + qBase) * HDIM;
    const int8_t* Kg = g_k2 + (long)bh * SEQ * HDIM;
    const int8_t* Vg = g_v2t + (long)bh * HDIM * SEQ;

    if (tid < 64) {
        int r = tid >> 2, s = tid & 3;
        cp16(&Qsm[r * 80 + s * 16], &Qg[r * 64 + s * 16]);
    }
    #pragma unroll
    for (int t2 = 0; t2 < 4; t2++) {
        int idx = tid + t2 * 256;
        int r = idx >> 2, s = idx & 3;
        cp16(&B0[r * 80 + s * 16], &Kg[r * 64 + s * 16]);
    }
    CP_COMMIT();
    #pragma unroll
    for (int t2 = 0; t2 < 4; t2++) {
        int idx = tid + t2 * 256;
        int r = idx >> 2, s = idx & 3;
        cp16(&B1[r * 80 + s * 16], &Kg[(256 + r) * 64 + s * 16]);
    }
    CP_COMMIT();
    if (tid < 16) rs[tid] = 0.f;
    CP_WAIT1();
    __syncthreads();

    uint32_t B0u = smem_u32(B0), B1u = smem_u32(B1);
    uint32_t Qu  = smem_u32(Qsm);
    uint32_t aoffQ = (uint32_t)(lane & 15) * 80 + ((lane >> 4) << 4);
    uint32_t kfoff = (uint32_t)(w * 32 + (lane & 7) + ((lane >> 4) << 3)) * 80
                     + (((lane >> 3) & 1) << 4);

    // Q fragments hoisted: loop-invariant across the 4 K-quarters
    uint32_t qf[2][4];
    #pragma unroll
    for (int ks2 = 0; ks2 < 2; ks2++)
        ldsm4(Qu + aoffQ + ks2 * 32, qf[ks2][0], qf[ks2][1], qf[ks2][2], qf[ks2][3]);

    int acc[16][4];
    #pragma unroll
    for (int j = 0; j < 16; j++)
        #pragma unroll
        for (int v = 0; v < 4; v++) acc[j][v] = 0;

    #pragma unroll
    for (int qi = 0; qi < 4; qi++) {
        uint32_t bufU = (qi & 1) ? B1u : B0u;
        int8_t*  buf  = (qi & 1) ? B1 : B0;
        #pragma unroll
        for (int ks2 = 0; ks2 < 2; ks2++) {
            #pragma unroll
            for (int p = 0; p < 2; p++) {
                uint32_t b0, b1, b2, b3;
                ldsm4(bufU + kfoff + (uint32_t)p * (16 * 80) + ks2 * 32, b0, b1, b2, b3);
                MMA_S8(acc[qi * 4 + 2 * p],
                       qf[ks2][0], qf[ks2][1], qf[ks2][2], qf[ks2][3], b0, b1);
                MMA_S8(acc[qi * 4 + 2 * p + 1],
                       qf[ks2][0], qf[ks2][1], qf[ks2][2], qf[ks2][3], b2, b3);
            }
        }
        __syncthreads();
        if (qi < 2) {
            #pragma unroll
            for (int t2 = 0; t2 < 4; t2++) {
                int idx = tid + t2 * 256;
                int r = idx >> 2, s = idx & 3;
                cp16(&buf[r * 80 + s * 16], &Kg[((qi + 2) * 256 + r) * 64 + s * 16]);
            }
            CP_COMMIT();
            CP_WAIT1();
            __syncthreads();
        } else if (qi == 2) {
            #pragma unroll
            for (int t2 = 0; t2 < 4; t2++) {
                int idx = tid + t2 * 256;
                int d = idx >> 4, s = idx & 15;
                cp16(&buf[d * 272 + s * 16], &Vg[d * 1024 + s * 16]);
            }
            CP_COMMIT();
            CP_WAIT1();
            __syncthreads();
        } else {
            #pragma unroll
            for (int t2 = 0; t2 < 4; t2++) {
                int idx = tid + t2 * 256;
                int d = idx >> 4, s = idx & 15;
                cp16(&buf[d * 272 + s * 16], &Vg[d * 1024 + 256 + s * 16]);
            }
            CP_COMMIT();
        }
    }

    float s6p = g_sc[6] * 8388608.0f;
    float sum0 = 0.f, sum1 = 0.f;
    #pragma unroll
    for (int j = 0; j < 16; j++) {
        float p0 = pexp2i(acc[j][0], s6p);
        float p1 = pexp2i(acc[j][1], s6p);
        float p2 = pexp2i(acc[j][2], s6p);
        float p3 = pexp2i(acc[j][3], s6p);
        acc[j][0] = __float_as_int(p0); acc[j][1] = __float_as_int(p1);
        acc[j][2] = __float_as_int(p2); acc[j][3] = __float_as_int(p3);
        sum0 += p0 + p1;
        sum1 += p2 + p3;
    }
    sum0 += __shfl_xor_sync(0xffffffffu, sum0, 1);
    sum0 += __shfl_xor_sync(0xffffffffu, sum0, 2);
    sum1 += __shfl_xor_sync(0xffffffffu, sum1, 1);
    sum1 += __shfl_xor_sync(0xffffffffu, sum1, 2);
    if (q4 == 0) {
        atomicAdd(&rs[g], sum0);
        atomicAdd(&rs[g + 8], sum1);
    }
    __syncthreads();
    if (tid < 16) rs[tid] = 1.0f / (rs[tid] * g_sc[4]);
    __syncthreads();

    float iv0 = rs[g], iv1 = rs[g + 8];
    #pragma unroll
    for (int j = 0; j < 16; j++) {
        int col = (j >> 2) * 256 + w * 32 + (j & 3) * 8 + q4 * 2;
        uint8_t v0 = (uint8_t)q8p(__int_as_float(acc[j][0]) * iv0);
        uint8_t v1 = (uint8_t)q8p(__int_as_float(acc[j][1]) * iv0);
        *(uint16_t*)&Asm[g * 1040 + col] = (uint16_t)v0 | ((uint16_t)v1 << 8);
        uint8_t v2 = (uint8_t)q8p(__int_as_float(acc[j][2]) * iv1);
        uint8_t v3 = (uint8_t)q8p(__int_as_float(acc[j][3]) * iv1);
        *(uint16_t*)&Asm[(g + 8) * 1040 + col] = (uint16_t)v2 | ((uint16_t)v3 << 8);
    }
    CP_WAIT1();
    __syncthreads();

    uint32_t Aoff  = smem_u32(Asm) + (uint32_t)(lane & 15) * 1040 + ((lane >> 4) << 4);
    uint32_t Vfoff = (uint32_t)(w * 8 + (lane & 7)) * 272 + ((lane >> 3) << 4);

    int pv[4] = {0, 0, 0, 0};
    #pragma unroll
    for (int qv = 0; qv < 4; qv++) {
        uint32_t bufU = (qv & 1) ? B1u : B0u;
        int8_t*  buf  = (qv & 1) ? B1 : B0;
        uint32_t Abase = Aoff + (uint32_t)qv * 256;
        #pragma unroll
        for (int ksl = 0; ksl < 256; ksl += 64) {
            uint32_t va, vb, vc, vd;
            ldsm4(bufU + Vfoff + ksl, va, vb, vc, vd);
            uint32_t a0, a1, a2, a3;
            ldsm4(Abase + ksl, a0, a1, a2, a3);
            MMA_S8(pv, a0, a1, a2, a3, va, vb);
            ldsm4(Abase + ksl + 32, a0, a1, a2, a3);
            MMA_S8(pv, a0, a1, a2, a3, vc, vd);
        }
        if (qv < 2) {
            __syncthreads();
            #pragma unroll
            for (int t2 = 0; t2 < 4; t2++) {
                int idx = tid + t2 * 256;
                int d = idx >> 4, s = idx & 15;
                cp16(&buf[d * 272 + s * 16], &Vg[d * 1024 + (qv + 2) * 256 + s * 16]);
            }
            CP_COMMIT();
            CP_WAIT1();
            __syncthreads();
        } else if (qv == 2) {
            CP_WAIT0();
            __syncthreads();
        }
    }

    float r9 = g_sc[9];
    long base0 = ((long)(b * SEQ + qBase + g)) * CH + h * HDIM + w * 8 + q4 * 2;
    uint16_t pA = (uint16_t)(uint8_t)q8((float)pv[0] * r9)
                | ((uint16_t)(uint8_t)q8((float)pv[1] * r9) << 8);
    *(uint16_t*)&g_x1q[base0] = pA;
    uint16_t pB = (uint16_t)(uint8_t)q8((float)pv[2] * r9)
                | ((uint16_t)(uint8_t)q8((float)pv[3] * r9) << 8);
    *(uint16_t*)&g_x1q[base0 + 8L * CH] = pB;
}

// ---------------- launcher (serial, monolithic) ----------------
extern "C" void kernel_launch(void* const* d_in, const int* in_sizes, int n_in,
                              void* d_out, int out_size) {
    const float* x0             = (const float*)d_in[0];
    const float* qkv_w          = (const float*)d_in[1];
    const float* qkv_b          = (const float*)d_in[2];
    const float* qkv_alpha      = (const float*)d_in[3];
    const float* qkv_act_alpha  = (const float*)d_in[4];
    const float* proj_w         = (const float*)d_in[5];
    const float* proj_b         = (const float*)d_in[6];
    const float* proj_alpha     = (const float*)d_in[7];
    const float* proj_act_alpha = (const float*)d_in[8];
    const float* norm_q_w       = (const float*)d_in[9];
    const float* norm_q_b       = (const float*)d_in[10];
    const float* norm_k_w       = (const float*)d_in[11];
    const float* norm_k_b       = (const float*)d_in[12];
    const float* q_alpha        = (const float*)d_in[13];
    const float* k_alpha        = (const float*)d_in[14];
    const float* v_alpha        = (const float*)d_in[15];
    const float* attn_alpha     = (const float*)d_in[16];
    float* out = (float*)d_out;

    cudaFuncSetAttribute(k_attn_fused, cudaFuncAttributeMaxDynamicSharedMemorySize, SMEM_ATT);
    cudaFuncSetAttribute(gemm_qkv, cudaFuncAttributeMaxDynamicSharedMemorySize, GSM0);
    cudaFuncSetAttribute(gemm_proj, cudaFuncAttributeMaxDynamicSharedMemorySize, GSM1);

    // 1
    k_pre<<<1, 256>>>(qkv_act_alpha, proj_act_alpha, q_alpha, k_alpha, v_alpha,
                      attn_alpha, qkv_alpha, proj_alpha, qkv_b);
    // 2: fused quantizer, 16B/thread
    k_quant_all<<<(NG_ALL + 255) / 256, 256>>>(x0, qkv_w, proj_w);
    // 3: QKV GEMM + fused norm (576 CTAs)
    gemm_qkv<<<dim3(C3v / 128, ROWS / 128, 1), 256, GSM0>>>(
        qkv_alpha, norm_q_w, norm_q_b, norm_k_w, norm_k_b);
    // 4: fused attention (3 CTAs/SM, hoisted Q fragments)
    k_attn_fused<<<dim3(SEQ / 16, NBH), 256, SMEM_ATT>>>();
    // 5: projection GEMM (384 CTAs, 3 CTAs/SM -> single wave)
    gemm_proj<<<dim3(CH / 64, ROWS / 128, 1), 256, GSM1>>>(out, proj_alpha, proj_b);
}

// round 17
// speedup vs baseline: 1.0304x; 1.0285x over previous
#include <cuda_runtime.h>
#include <stdint.h>

// ---------------- problem constants ----------------
constexpr int BATCH = 4, SEQ = 1024, CH = 768, HEADS = 12, HDIM = 64;
constexpr int ROWS = BATCH * SEQ;   // 4096
constexpr int C3v  = 3 * CH;        // 2304
constexpr int NBH  = BATCH * HEADS; // 48

// ---------------- scratch ----------------
__device__ __align__(256) int8_t g_x0q [ROWS * CH];
__device__ __align__(256) int8_t g_wqkv[C3v * CH];
__device__            int    g_biasi[C3v];
__device__ __align__(256) int8_t g_wproj[CH * CH];
__device__ __align__(256) float  g_rw  [C3v + CH];
__device__ __align__(256) int8_t g_q2  [NBH * SEQ * HDIM];
__device__ __align__(256) int8_t g_k2  [NBH * SEQ * HDIM];
__device__ __align__(256) int8_t g_v2t [NBH * HDIM * SEQ];
__device__ __align__(256) int8_t g_x1q [ROWS * CH];
// 0:a_in 1:aq 2:ak 3:av 4:am 5:ap 6:LOG2E*hs*aq*ak 7:am*av 8:1/a_in 9:(am*av)/ap
__device__            float  g_sc[12];

__device__ __forceinline__ float clip8(float x) { return fminf(fmaxf(x, -8.f), 7.f); }
__device__ __forceinline__ int8_t q8(float x) { return (int8_t)__float2int_rn(clip8(x)); }
__device__ __forceinline__ int8_t q8p(float x) { return (int8_t)__float2int_rn(fminf(x, 7.f)); }

__device__ __forceinline__ float pexp2i(int acc, float s6p) {
    return __int_as_float(__float2int_rn(fmaf((float)acc, s6p, 1065353216.0f)));
}

__device__ __forceinline__ void cp16(void* dst, const void* src) {
    uint32_t d = (uint32_t)__cvta_generic_to_shared(dst);
    asm volatile("cp.async.cg.shared.global [%0], [%1], 16;" :: "r"(d), "l"(src));
}
#define CP_COMMIT() asm volatile("cp.async.commit_group;")
#define CP_WAIT1()  asm volatile("cp.async.wait_group 1;")
#define CP_WAIT0()  asm volatile("cp.async.wait_group 0;")

__device__ __forceinline__ uint32_t smem_u32(const void* p) {
    return (uint32_t)__cvta_generic_to_shared(p);
}
__device__ __forceinline__ void ldsm4(uint32_t addr, uint32_t& r0, uint32_t& r1,
                                      uint32_t& r2, uint32_t& r3) {
    asm volatile("ldmatrix.sync.aligned.m8n8.x4.shared.b16 {%0,%1,%2,%3}, [%4];"
                 : "=r"(r0), "=r"(r1), "=r"(r2), "=r"(r3) : "r"(addr));
}
#define MMA_S8(acc, a0, a1, a2, a3, b0, b1) \
    asm volatile("mma.sync.aligned.m16n8k32.row.col.s32.s8.s8.s32 " \
                 "{%0,%1,%2,%3},{%4,%5,%6,%7},{%8,%9},{%0,%1,%2,%3};" \
                 : "+r"((acc)[0]), "+r"((acc)[1]), "+r"((acc)[2]), "+r"((acc)[3]) \
                 : "r"(a0), "r"(a1), "r"(a2), "r"(a3), "r"(b0), "r"(b1))

// ---------------- pre (1024 threads) ----------------
__global__ void __launch_bounds__(1024) k_pre(
                      const float* __restrict__ qkv_act_alpha,
                      const float* __restrict__ proj_act_alpha,
                      const float* __restrict__ q_alpha,
                      const float* __restrict__ k_alpha,
                      const float* __restrict__ v_alpha,
                      const float* __restrict__ attn_alpha,
                      const float* __restrict__ qkv_alpha,
                      const float* __restrict__ proj_alpha,
                      const float* __restrict__ qkv_b) {
    __shared__ float sh[1024];
    int t = threadIdx.x;
    for (int i = t; i < C3v + CH; i += 1024)
        g_rw[i] = 1.0f / (i < C3v ? qkv_alpha[i] : proj_alpha[i - C3v]);
    float s = (t < CH) ? qkv_act_alpha[t] : 0.f;
    sh[t] = s; __syncthreads();
    for (int o = 512; o > 0; o >>= 1) { if (t < o) sh[t] += sh[t + o]; __syncthreads(); }
    float a_in = sh[0] / (float)CH;
    __syncthreads();
    for (int o = t; o < C3v; o += 1024)
        g_biasi[o] = (int)truncf(qkv_b[o] / a_in / qkv_alpha[o]);
    s = (t < CH) ? proj_act_alpha[t] : 0.f;
    sh[t] = s; __syncthreads();
    for (int o = 512; o > 0; o >>= 1) { if (t < o) sh[t] += sh[t + o]; __syncthreads(); }
    float ap = sh[0] / (float)CH;
    if (t == 0) {
        float aq = 0.f, ak = 0.f, av = 0.f, am = 0.f;
        for (int i = 0; i < HEADS; i++) { aq += q_alpha[i]; ak += k_alpha[i]; av += v_alpha[i]; am += attn_alpha[i]; }
        aq /= HEADS; ak /= HEADS; av /= HEADS; am /= HEADS;
        g_sc[0] = a_in; g_sc[1] = aq; g_sc[2] = ak; g_sc[3] = av; g_sc[4] = am; g_sc[5] = ap;
        g_sc[6] = 1.4426950408889634f * ((0.125f * aq) * ak);
        g_sc[7] = am * av;
        g_sc[8] = 1.0f / a_in;
        g_sc[9] = (am * av) / ap;
    }
}

// ---------------- fused quantizer: 16 outputs per thread ----------------
constexpr int NG_X0 = ROWS * CH / 16;
constexpr int NG_WQ = C3v * CH / 16;
constexpr int NG_WP = CH * CH / 16;
constexpr int NG_ALL = NG_X0 + NG_WQ + NG_WP;

__device__ __forceinline__ uint32_t pack4(float a, float b, float c, float d) {
    return (uint32_t)(uint8_t)q8(a) | ((uint32_t)(uint8_t)q8(b) << 8) |
           ((uint32_t)(uint8_t)q8(c) << 16) | ((uint32_t)(uint8_t)q8(d) << 24);
}

__global__ void k_quant_all(const float* __restrict__ x0,
                            const float* __restrict__ qkv_w,
                            const float* __restrict__ proj_w) {
    int i = blockIdx.x * blockDim.x + threadIdx.x;
    if (i >= NG_ALL) return;
    const float4* src;
    uint4* dst;
    float r;
    if (i < NG_X0) {
        src = (const float4*)x0 + i * 4;
        dst = (uint4*)g_x0q + i;
        r = g_sc[8];
    } else if (i < NG_X0 + NG_WQ) {
        int k = i - NG_X0;
        src = (const float4*)qkv_w + k * 4;
        dst = (uint4*)g_wqkv + k;
        r = g_rw[k / (CH / 16)];
    } else {
        int k = i - NG_X0 - NG_WQ;
        src = (const float4*)proj_w + k * 4;
        dst = (uint4*)g_wproj + k;
        r = g_rw[C3v + k / (CH / 16)];
    }
    float4 v0 = src[0], v1 = src[1], v2 = src[2], v3 = src[3];
    uint4 o;
    o.x = pack4(v0.x * r, v0.y * r, v0.z * r, v0.w * r);
    o.y = pack4(v1.x * r, v1.y * r, v1.z * r, v1.w * r);
    o.z = pack4(v2.x * r, v2.y * r, v2.z * r, v2.w * r);
    o.w = pack4(v3.x * r, v3.y * r, v3.z * r, v3.w * r);
    *dst = o;
}

// ---------------- QKV GEMM (128x128, 3-stage cp.async, fused norm epilogue) ----------------
constexpr int GSM0 = 128 * 130 * 4;
__global__ void __launch_bounds__(256, 2) gemm_qkv(
        const float* __restrict__ qkv_alpha,
        const float* __restrict__ nqw, const float* __restrict__ nqb,
        const float* __restrict__ nkw, const float* __restrict__ nkb) {
    constexpr int K = 768, BM = 128, BN = 128, BK = 64, NTHR = 256;
    constexpr int WM = 64, WN = 32, MI = 4, NI = 4;
    constexpr int SAS = BK + 16;
    constexpr int NK = K / BK;

    extern __shared__ __align__(16) int8_t dsm[];
    int8_t* As = dsm;
    int8_t* Bs = dsm + 3 * BM * SAS;

    __shared__ float sA[130], sP1[130], sP2[130];
    __shared__ int   sBi[130], coef[64];

    int tid = threadIdx.x;
    int warp = tid >> 5, lane = tid & 31;
    int wr = warp / 4, wc = warp % 4;
    int g = lane >> 2, q4 = lane & 3;
    int rowBase = blockIdx.y * BM;
    int colBase = blockIdx.x * BN;

    if (tid < 128) {
        int col = colBase + tid;
        int d = tid & 63, hs = tid >> 6;
        int idx = d * 2 + hs;
        int branch = col / CH;
        sBi[idx] = g_biasi[col];
        if (branch == 0) {
            float w = nqw[d];
            sA[idx]  = qkv_alpha[col];
            sP1[idx] = nqb[d] / w;
            sP2[idx] = w / g_sc[1];
        } else if (branch == 1) {
            float w = nkw[d];
            sA[idx]  = qkv_alpha[col];
            sP1[idx] = nkb[d] / w;
            sP2[idx] = w / g_sc[2];
        } else {
            sA[idx]  = (g_sc[0] * qkv_alpha[col]) / g_sc[3];
            sP1[idx] = 0.f; sP2[idx] = 0.f;
        }
    }
    if (tid < 64) coef[tid] = 1024 / (tid + 1);

    uint32_t As_base = smem_u32(As);
    uint32_t Bs_base = smem_u32(Bs);
    uint32_t aoff = (uint32_t)(wr * WM + (lane & 15)) * SAS + ((lane >> 4) << 4);
    uint32_t boff = (uint32_t)(wc * WN + (lane & 7) + ((lane >> 4) << 3)) * SAS
                    + (((lane >> 3) & 1) << 4);

    auto load_stage = [&](int st, int k0) {
        #pragma unroll
        for (int idx = tid; idx < BM * BK / 16; idx += NTHR) {
            int r = idx / (BK / 16), seg = idx % (BK / 16);
            cp16(&As[st * BM * SAS + r * SAS + seg * 16],
                 &g_x0q[(long)(rowBase + r) * K + k0 + seg * 16]);
        }
        #pragma unroll
        for (int idx = tid; idx < BN * BK / 16; idx += NTHR) {
            int r = idx / (BK / 16), seg = idx % (BK / 16);
            cp16(&Bs[st * BN * SAS + r * SAS + seg * 16],
                 &g_wqkv[(long)(colBase + r) * K + k0 + seg * 16]);
        }
    };

    int acc[MI][NI][4];
    #pragma unroll
    for (int i = 0; i < MI; i++)
        #pragma unroll
        for (int j = 0; j < NI; j++)
            #pragma unroll
            for (int v = 0; v < 4; v++) acc[i][j][v] = 0;

    load_stage(0, 0); CP_COMMIT();
    load_stage(1, BK); CP_COMMIT();

    for (int it = 0; it < NK; it++) {
        if (it < NK - 1) { CP_WAIT1(); } else { CP_WAIT0(); }
        __syncthreads();
        if (it + 2 < NK) { load_stage((it + 2) % 3, (it + 2) * BK); CP_COMMIT(); }

        int slot = it % 3;
        uint32_t Abase = As_base + (uint32_t)slot * (BM * SAS) + aoff;
        uint32_t Bbase = Bs_base + (uint32_t)slot * (BN * SAS) + boff;

        #pragma unroll
        for (int ks = 0; ks < BK; ks += 32) {
            uint32_t bfr[2][4];
            #pragma unroll
            for (int jj = 0; jj < 2; jj++)
                ldsm4(Bbase + jj * (16 * SAS) + ks,
                      bfr[jj][0], bfr[jj][1], bfr[jj][2], bfr[jj][3]);
            #pragma unroll
            for (int i = 0; i < MI; i++) {
                uint32_t a0, a1, a2, a3;
                ldsm4(Abase + i * (16 * SAS) + ks, a0, a1, a2, a3);
                #pragma unroll
                for (int j = 0; j < NI; j++)
                    MMA_S8(acc[i][j], a0, a1, a2, a3,
                           bfr[j >> 1][(j & 1) * 2], bfr[j >> 1][(j & 1) * 2 + 1]);
            }
        }
    }
    __syncthreads();

    int* sm32 = (int*)dsm;
    int rbL = wr * WM, cbL = wc * WN;
    #pragma unroll
    for (int i = 0; i < MI; i++)
        #pragma unroll
        for (int j = 0; j < NI; j++)
            #pragma unroll
            for (int v = 0; v < 4; v++) {
                int rr = rbL + i * 16 + g + (v >> 1) * 8;
                int cc = cbL + j * 8 + q4 * 2 + (v & 1);
                sm32[rr * 130 + cc + (cc >> 6)] = acc[i][j][v];
            }
    __syncthreads();

    int r = tid >> 1, hs = tid & 1;
    int slice = (colBase >> 6) + hs;
    int branch = slice / HEADS;
    int hh = slice % HEADS;
    int rrG = rowBase + r;
    int bb = rrG >> 10, nn = rrG & 1023;
    int bhh = bb * HEADS + hh;
    const int base = r * 130 + hs * 65;

    if (branch < 2) {
        int m = 0, vv = 0;
        #pragma unroll 8
        for (int d = 0; d < HDIM; d++) {
            int ival = sm32[base + d] + sBi[d * 2 + hs];
            float xf = (float)ival * sA[d * 2 + hs];
            int xi = (int)xf;
            int dd = xi - m;
            m += (dd * coef[d]) >> 10;
            vv += dd * (xi - m);
        }
        float mu = (float)m;
        float invden = 1.0f / (sqrtf((float)vv * 0.015625f) + 1e-5f);
        uint32_t* outp = (uint32_t*)((branch == 0 ? g_q2 : g_k2)
                          + ((long)bhh * SEQ + nn) * HDIM);
        #pragma unroll 4
        for (int dw = 0; dw < 16; dw++) {
            uint32_t pk = 0;
            #pragma unroll
            for (int kk = 0; kk < 4; kk++) {
                int d = dw * 4 + kk;
                int ival = sm32[base + d] + sBi[d * 2 + hs];
                float xf = (float)ival * sA[d * 2 + hs];
                float q1 = (xf - mu) * invden;
                pk |= ((uint32_t)(uint8_t)q8((q1 + sP1[d * 2 + hs]) * sP2[d * 2 + hs]))
                      << (kk * 8);
            }
            outp[dw] = pk;
        }
    } else {
        int8_t* outv = g_v2t + (long)bhh * HDIM * SEQ + nn;
        #pragma unroll 8
        for (int d = 0; d < HDIM; d++) {
            int ival = sm32[base + d] + sBi[d * 2 + hs];
            outv[d * SEQ] = q8((float)ival * sA[d * 2 + hs]);
        }
    }
}

// ---------------- proj GEMM (128x64, 3-stage cp.async, 3 CTAs/SM) ----------------
constexpr int GSM1 = 3 * (128 + 64) * 80;   // 46080
__global__ void __launch_bounds__(256, 3) gemm_proj(float* __restrict__ outf,
        const float* __restrict__ e1, const float* __restrict__ e2) {
    constexpr int K = 768, BM = 128, BN = 64, BK = 64, NTHR = 256;
    constexpr int WM = 64, WN = 16, MI = 4, NI = 2;
    constexpr int SAS = BK + 16;
    constexpr int NK = K / BK;

    extern __shared__ __align__(16) int8_t dsm[];
    int8_t* As = dsm;
    int8_t* Bs = dsm + 3 * BM * SAS;

    __shared__ float sA[64], sP1[64];

    int tid = threadIdx.x;
    int warp = tid >> 5, lane = tid & 31;
    int wr = warp / 4, wc = warp % 4;
    int g = lane >> 2, q4 = lane & 3;
    int rowBase = blockIdx.y * BM;
    int colBase = blockIdx.x * BN;

    if (tid < BN) {
        int cc = colBase + tid;
        sA[tid]  = e1[cc] * g_sc[5];
        sP1[tid] = e2[cc];
    }

    uint32_t As_base = smem_u32(As);
    uint32_t Bs_base = smem_u32(Bs);
    uint32_t aoff = (uint32_t)(wr * WM + (lane & 15)) * SAS + ((lane >> 4) << 4);
    uint32_t boff = (uint32_t)(wc * WN + (lane & 7) + ((lane >> 4) << 3)) * SAS
                    + (((lane >> 3) & 1) << 4);

    auto load_stage = [&](int st, int k0) {
        #pragma unroll
        for (int idx = tid; idx < BM * BK / 16; idx += NTHR) {
            int r = idx / (BK / 16), seg = idx % (BK / 16);
            cp16(&As[st * BM * SAS + r * SAS + seg * 16],
                 &g_x1q[(long)(rowBase + r) * K + k0 + seg * 16]);
        }
        #pragma unroll
        for (int idx = tid; idx < BN * BK / 16; idx += NTHR) {
            int r = idx / (BK / 16), seg = idx % (BK / 16);
            cp16(&Bs[st * BN * SAS + r * SAS + seg * 16],
                 &g_wproj[(long)(colBase + r) * K + k0 + seg * 16]);
        }
    };

    int acc[MI][NI][4];
    #pragma unroll
    for (int i = 0; i < MI; i++)
        #pragma unroll
        for (int j = 0; j < NI; j++)
            #pragma unroll
            for (int v = 0; v < 4; v++) acc[i][j][v] = 0;

    load_stage(0, 0); CP_COMMIT();
    load_stage(1, BK); CP_COMMIT();

    for (int it = 0; it < NK; it++) {
        if (it < NK - 1) { CP_WAIT1(); } else { CP_WAIT0(); }
        __syncthreads();
        if (it + 2 < NK) { load_stage((it + 2) % 3, (it + 2) * BK); CP_COMMIT(); }

        int slot = it % 3;
        uint32_t Abase = As_base + (uint32_t)slot * (BM * SAS) + aoff;
        uint32_t Bbase = Bs_base + (uint32_t)slot * (BN * SAS) + boff;

        #pragma unroll
        for (int ks = 0; ks < BK; ks += 32) {
            uint32_t bfr[4];
            ldsm4(Bbase + ks, bfr[0], bfr[1], bfr[2], bfr[3]);
            #pragma unroll
            for (int i = 0; i < MI; i++) {
                uint32_t a0, a1, a2, a3;
                ldsm4(Abase + i * (16 * SAS) + ks, a0, a1, a2, a3);
                MMA_S8(acc[i][0], a0, a1, a2, a3, bfr[0], bfr[1]);
                MMA_S8(acc[i][1], a0, a1, a2, a3, bfr[2], bfr[3]);
            }
        }
    }
    __syncthreads();

    int rb = rowBase + wr * WM;
    int cb = wc * WN;
    #pragma unroll
    for (int i = 0; i < MI; i++)
        #pragma unroll
        for (int j = 0; j < NI; j++)
            #pragma unroll
            for (int v = 0; v < 4; v++) {
                int rr = rb + i * 16 + g + (v >> 1) * 8;
                int ccl = cb + j * 8 + q4 * 2 + (v & 1);
                outf[(long)rr * CH + colBase + ccl] =
                    (float)acc[i][j][v] * sA[ccl] + sP1[ccl];
            }
}

// ---------------- fused flash attention: quarter-streamed K/V, 3 CTAs/SM ----------------
constexpr int ATT_B0 = 0;
constexpr int ATT_B1 = 20480;
constexpr int ATT_A  = 40960;
constexpr int ATT_Q  = 57600;
constexpr int ATT_S  = 58880;
constexpr int SMEM_ATT = 58944;

__global__ void __launch_bounds__(256, 3) k_attn_fused() {
    extern __shared__ __align__(16) int8_t sh[];
    int8_t* B0  = sh + ATT_B0;
    int8_t* B1  = sh + ATT_B1;
    int8_t* Asm = sh + ATT_A;
    int8_t* Qsm = sh + ATT_Q;
    float*  rs  = (float*)(sh + ATT_S);

    int bh = blockIdx.y;
    int h = bh % HEADS, b = bh / HEADS;
    int qBase = blockIdx.x * 16;
    int tid = threadIdx.x, w = tid >> 5, lane = tid & 31;
    int g = lane >> 2, q4 = lane & 3;

    const int8_t* Qg = g_q2 + ((long)bh * SEQ + qBase) * HDIM;
    const int8_t* Kg = g_k2 + (long)bh * SEQ * HDIM;
    const int8_t* Vg = g_v2t + (long)bh * HDIM * SEQ;

    if (tid < 16) rs[tid] = 0.f;
    if (tid < 64) {
        int r = tid >> 2, s = tid & 3;
        cp16(&Qsm[r * 80 + s * 16], &Qg[r * 64 + s * 16]);
    }
    #pragma unroll
    for (int t2 = 0; t2 < 4; t2++) {
        int idx = tid + t2 * 256;
        int r = idx >> 2, s = idx & 3;
        cp16(&B0[r * 80 + s * 16], &Kg[r * 64 + s * 16]);
    }
    CP_COMMIT();
    #pragma unroll
    for (int t2 = 0; t2 < 4; t2++) {
        int idx = tid + t2 * 256;
        int r = idx >> 2, s = idx & 3;
        cp16(&B1[r * 80 + s * 16], &Kg[(256 + r) * 64 + s * 16]);
    }
    CP_COMMIT();
    CP_WAIT1();
    __syncthreads();

    uint32_t B0u = smem_u32(B0), B1u = smem_u32(B1);
    uint32_t Qu  = smem_u32(Qsm);
    uint32_t aoffQ = (uint32_t)(lane & 15) * 80 + ((lane >> 4) << 4);
    uint32_t kfoff = (uint32_t)(w * 32 + (lane & 7) + ((lane >> 4) << 3)) * 80
                     + (((lane >> 3) & 1) << 4);

    // Q fragments hoisted: loop-invariant across the 4 K-quarters
    uint32_t qf[2][4];
    #pragma unroll
    for (int ks2 = 0; ks2 < 2; ks2++)
        ldsm4(Qu + aoffQ + ks2 * 32, qf[ks2][0], qf[ks2][1], qf[ks2][2], qf[ks2][3]);

    int acc[16][4];
    #pragma unroll
    for (int j = 0; j < 16; j++)
        #pragma unroll
        for (int v = 0; v < 4; v++) acc[j][v] = 0;

    #pragma unroll
    for (int qi = 0; qi < 4; qi++) {
        uint32_t bufU = (qi & 1) ? B1u : B0u;
        int8_t*  buf  = (qi & 1) ? B1 : B0;
        #pragma unroll
        for (int ks2 = 0; ks2 < 2; ks2++) {
            #pragma unroll
            for (int p = 0; p < 2; p++) {
                uint32_t b0, b1, b2, b3;
                ldsm4(bufU + kfoff + (uint32_t)p * (16 * 80) + ks2 * 32, b0, b1, b2, b3);
                MMA_S8(acc[qi * 4 + 2 * p],
                       qf[ks2][0], qf[ks2][1], qf[ks2][2], qf[ks2][3], b0, b1);
                MMA_S8(acc[qi * 4 + 2 * p + 1],
                       qf[ks2][0], qf[ks2][1], qf[ks2][2], qf[ks2][3], b2, b3);
            }
        }
        __syncthreads();
        if (qi < 2) {
            #pragma unroll
            for (int t2 = 0; t2 < 4; t2++) {
                int idx = tid + t2 * 256;
                int r = idx >> 2, s = idx & 3;
                cp16(&buf[r * 80 + s * 16], &Kg[((qi + 2) * 256 + r) * 64 + s * 16]);
            }
            CP_COMMIT();
            CP_WAIT1();
            __syncthreads();
        } else if (qi == 2) {
            #pragma unroll
            for (int t2 = 0; t2 < 4; t2++) {
                int idx = tid + t2 * 256;
                int d = idx >> 4, s = idx & 15;
                cp16(&buf[d * 272 + s * 16], &Vg[d * 1024 + s * 16]);
            }
            CP_COMMIT();
            CP_WAIT1();
            __syncthreads();
        } else {
            #pragma unroll
            for (int t2 = 0; t2 < 4; t2++) {
                int idx = tid + t2 * 256;
                int d = idx >> 4, s = idx & 15;
                cp16(&buf[d * 272 + s * 16], &Vg[d * 1024 + 256 + s * 16]);
            }
            CP_COMMIT();
        }
    }

    float s6p = g_sc[6] * 8388608.0f;
    float sum0 = 0.f, sum1 = 0.f;
    #pragma unroll
    for (int j = 0; j < 16; j++) {
        float p0 = pexp2i(acc[j][0], s6p);
        float p1 = pexp2i(acc[j][1], s6p);
        float p2 = pexp2i(acc[j][2], s6p);
        float p3 = pexp2i(acc[j][3], s6p);
        acc[j][0] = __float_as_int(p0); acc[j][1] = __float_as_int(p1);
        acc[j][2] = __float_as_int(p2); acc[j][3] = __float_as_int(p3);
        sum0 += p0 + p1;
        sum1 += p2 + p3;
    }
    sum0 += __shfl_xor_sync(0xffffffffu, sum0, 1);
    sum0 += __shfl_xor_sync(0xffffffffu, sum0, 2);
    sum1 += __shfl_xor_sync(0xffffffffu, sum1, 1);
    sum1 += __shfl_xor_sync(0xffffffffu, sum1, 2);
    if (q4 == 0) {
        atomicAdd(&rs[g], sum0);
        atomicAdd(&rs[g + 8], sum1);
    }
    __syncthreads();
    if (tid < 16) rs[tid] = 1.0f / (rs[tid] * g_sc[4]);
    __syncthreads();

    float iv0 = rs[g], iv1 = rs[g + 8];
    #pragma unroll
    for (int j = 0; j < 16; j++) {
        int col = (j >> 2) * 256 + w * 32 + (j & 3) * 8 + q4 * 2;
        uint8_t v0 = (uint8_t)q8p(__int_as_float(acc[j][0]) * iv0);
        uint8_t v1 = (uint8_t)q8p(__int_as_float(acc[j][1]) * iv0);
        *(uint16_t*)&Asm[g * 1040 + col] = (uint16_t)v0 | ((uint16_t)v1 << 8);
        uint8_t v2 = (uint8_t)q8p(__int_as_float(acc[j][2]) * iv1);
        uint8_t v3 = (uint8_t)q8p(__int_as_float(acc[j][3]) * iv1);
        *(uint16_t*)&Asm[(g + 8) * 1040 + col] = (uint16_t)v2 | ((uint16_t)v3 << 8);
    }
    CP_WAIT1();
    __syncthreads();

    uint32_t Aoff  = smem_u32(Asm) + (uint32_t)(lane & 15) * 1040 + ((lane >> 4) << 4);
    uint32_t Vfoff = (uint32_t)(w * 8 + (lane & 7)) * 272 + ((lane >> 3) << 4);

    int pv[4] = {0, 0, 0, 0};
    #pragma unroll
    for (int qv = 0; qv < 4; qv++) {
        uint32_t bufU = (qv & 1) ? B1u : B0u;
        int8_t*  buf  = (qv & 1) ? B1 : B0;
        uint32_t Abase = Aoff + (uint32_t)qv * 256;
        #pragma unroll
        for (int ksl = 0; ksl < 256; ksl += 64) {
            uint32_t va, vb, vc, vd;
            ldsm4(bufU + Vfoff + ksl, va, vb, vc, vd);
            uint32_t a0, a1, a2, a3;
            ldsm4(Abase + ksl, a0, a1, a2, a3);
            MMA_S8(pv, a0, a1, a2, a3, va, vb);
            ldsm4(Abase + ksl + 32, a0, a1, a2, a3);
            MMA_S8(pv, a0, a1, a2, a3, vc, vd);
        }
        if (qv < 2) {
            __syncthreads();
            #pragma unroll
            for (int t2 = 0; t2 < 4; t2++) {
                int idx = tid + t2 * 256;
                int d = idx >> 4, s = idx & 15;
                cp16(&buf[d * 272 + s * 16], &Vg[d * 1024 + (qv + 2) * 256 + s * 16]);
            }
            CP_COMMIT();
            CP_WAIT1();
            __syncthreads();
        } else if (qv == 2) {
            CP_WAIT0();
            __syncthreads();
        }
    }

    float r9 = g_sc[9];
    long base0 = ((long)(b * SEQ + qBase + g)) * CH + h * HDIM + w * 8 + q4 * 2;
    uint16_t pA = (uint16_t)(uint8_t)q8((float)pv[0] * r9)
                | ((uint16_t)(uint8_t)q8((float)pv[1] * r9) << 8);
    *(uint16_t*)&g_x1q[base0] = pA;
    uint16_t pB = (uint16_t)(uint8_t)q8((float)pv[2] * r9)
                | ((uint16_t)(uint8_t)q8((float)pv[3] * r9) << 8);
    *(uint16_t*)&g_x1q[base0 + 8L * CH] = pB;
}

// ---------------- launcher (serial, monolithic) ----------------
extern "C" void kernel_launch(void* const* d_in, const int* in_sizes, int n_in,
                              void* d_out, int out_size) {
    const float* x0             = (const float*)d_in[0];
    const float* qkv_w          = (const float*)d_in[1];
    const float* qkv_b          = (const float*)d_in[2];
    const float* qkv_alpha      = (const float*)d_in[3];
    const float* qkv_act_alpha  = (const float*)d_in[4];
    const float* proj_w         = (const float*)d_in[5];
    const float* proj_b         = (const float*)d_in[6];
    const float* proj_alpha     = (const float*)d_in[7];
    const float* proj_act_alpha = (const float*)d_in[8];
    const float* norm_q_w       = (const float*)d_in[9];
    const float* norm_q_b       = (const float*)d_in[10];
    const float* norm_k_w       = (const float*)d_in[11];
    const float* norm_k_b       = (const float*)d_in[12];
    const float* q_alpha        = (const float*)d_in[13];
    const float* k_alpha        = (const float*)d_in[14];
    const float* v_alpha        = (const float*)d_in[15];
    const float* attn_alpha     = (const float*)d_in[16];
    float* out = (float*)d_out;

    cudaFuncSetAttribute(k_attn_fused, cudaFuncAttributeMaxDynamicSharedMemorySize, SMEM_ATT);
    cudaFuncSetAttribute(gemm_qkv, cudaFuncAttributeMaxDynamicSharedMemorySize, GSM0);
    cudaFuncSetAttribute(gemm_proj, cudaFuncAttributeMaxDynamicSharedMemorySize, GSM1);

    // 1
    k_pre<<<1, 1024>>>(qkv_act_alpha, proj_act_alpha, q_alpha, k_alpha, v_alpha,
                       attn_alpha, qkv_alpha, proj_alpha, qkv_b);
    // 2: fused quantizer, 16B/thread
    k_quant_all<<<(NG_ALL + 255) / 256, 256>>>(x0, qkv_w, proj_w);
    // 3: QKV GEMM + fused norm (576 CTAs)
    gemm_qkv<<<dim3(C3v / 128, ROWS / 128, 1), 256, GSM0>>>(
        qkv_alpha, norm_q_w, norm_q_b, norm_k_w, norm_k_b);
    // 4: fused attention (3 CTAs/SM, hoisted Q fragments)
    k_attn_fused<<<dim3(SEQ / 16, NBH), 256, SMEM_ATT>>>();
    // 5: projection GEMM (384 CTAs, 3 CTAs/SM -> single wave)
    gemm_proj<<<dim3(CH / 64, ROWS / 128, 1), 256, GSM1>>>(out, proj_alpha, proj_b);
}